// round 1
// baseline (speedup 1.0000x reference)
#include <cuda_runtime.h>
#include <math.h>

// ---------------- problem constants ----------------
#define NTOK   98
#define DIMC   96
#define HD     32
#define NHEAD  3
#define HID    384
#define NWIN   2048           // 8 batches * 4*8*8 windows
#define NTOKENS 200704        // 8*8*56*56
#define XELEMS 19267584       // NTOKENS*96

#define NTHR1  512
#define NWARP1 16
#define NTHR2  256

// shared-memory strides (floats)
#define TS   116              // token-dim stride (mult of 4, %32==20)
#define AS   116              // attn n-stride
#define VS   100              // v2 channel stride
#define TS2  36               // mlp token stride

// kernel-1 smem layout (floats)
#define SM_XN 0               // [96][TS]    = 11136   (reused as attn-out, [c][t])
#define SM_QK 11136           // [192][TS]   = 22272   (q rows 0..95 scaled, k rows 96..191)
#define SM_AT 33408           // [100][AS]   = 11600   (S^T then P^T, [m][n])
#define SM_V2 45008           // [98][VS]    = 9800    ([t][c] all heads)
#define SM1_FLOATS 54808      // 219232 bytes

// kernel-2 smem layout
#define SM2_X 0               // [96][TS2]  = 3456
#define SM2_H 3456            // [384][TS2] = 13824
#define SM2_FLOATS 17280      // 69120 bytes

// ---------------- device scratch ----------------
__device__ float g_xmid[XELEMS];
__device__ float g_qkvT[96 * 288];     // [k][o]
__device__ float g_projT[96 * 96];
__device__ float g_fc1T[96 * 384];
__device__ float g_fc2T[384 * 96];
__device__ float g_bias[3 * 98 * 98];  // [h][n][m]

// ---------------- prep: transposes + bias table ----------------
__global__ void prep_kernel(const float* __restrict__ qkv_w,
                            const float* __restrict__ proj_w,
                            const float* __restrict__ fc1_w,
                            const float* __restrict__ fc2_w,
                            const float* __restrict__ rpb)
{
    int stride = gridDim.x * blockDim.x;
    int tid = blockIdx.x * blockDim.x + threadIdx.x;
    for (int idx = tid; idx < 96 * 288; idx += stride) {
        int k = idx / 288, o = idx - k * 288;
        g_qkvT[idx] = qkv_w[o * 96 + k];
    }
    for (int idx = tid; idx < 96 * 96; idx += stride) {
        int k = idx / 96, o = idx - k * 96;
        g_projT[idx] = proj_w[o * 96 + k];
    }
    for (int idx = tid; idx < 96 * 384; idx += stride) {
        int k = idx / 384, o = idx - k * 384;
        g_fc1T[idx] = fc1_w[o * 96 + k];
    }
    for (int idx = tid; idx < 384 * 96; idx += stride) {
        int k = idx / 96, o = idx - k * 96;
        g_fc2T[idx] = fc2_w[o * 384 + k];
    }
    for (int idx = tid; idx < 3 * 98 * 98; idx += stride) {
        int h = idx / (98 * 98);
        int r = idx - h * 98 * 98;
        int n = r / 98, m = r - n * 98;
        int nd = n / 49, nh = (n % 49) / 7, nw = n % 7;
        int md = m / 49, mh = (m % 49) / 7, mw = m % 7;
        int rel = (nd - md + 1) * 169 + (nh - mh + 6) * 13 + (nw - mw + 6);
        g_bias[idx] = rpb[rel * 3 + h];
    }
}

// ---------------- warp-tile GEMM: 32(M) x 16(N), 4x4 per lane ----------------
// A: [k][m] (smem), B: [k][n] (smem or L2-resident global)
template <bool BGLOBAL>
__device__ __forceinline__ void gemm_tile(const float* __restrict__ A, int lda,
                                          const float* __restrict__ B, int ldb,
                                          int K, int am, int bn, float acc[4][4])
{
#pragma unroll 4
    for (int k = 0; k < K; ++k) {
        float4 a4 = *reinterpret_cast<const float4*>(A + k * lda + am);
        float4 b4;
        if (BGLOBAL) b4 = __ldg(reinterpret_cast<const float4*>(B + k * ldb + bn));
        else         b4 = *reinterpret_cast<const float4*>(B + k * ldb + bn);
        float av[4] = {a4.x, a4.y, a4.z, a4.w};
        float bv[4] = {b4.x, b4.y, b4.z, b4.w};
#pragma unroll
        for (int i = 0; i < 4; ++i)
#pragma unroll
            for (int j = 0; j < 4; ++j)
                acc[i][j] = fmaf(av[i], bv[j], acc[i][j]);
    }
}

// ---------------- kernel 1: LN1 + QKV + attention + proj + residual ----------------
__global__ __launch_bounds__(NTHR1)
void attn_kernel(const float* __restrict__ x,
                 const float* __restrict__ n1w, const float* __restrict__ n1b,
                 const float* __restrict__ qkv_b,
                 const float* __restrict__ proj_b)
{
    extern __shared__ float sm[];
    float* s_xn = sm + SM_XN;   // later reused as attention-out [c][t]
    float* s_qk = sm + SM_QK;
    float* s_at = sm + SM_AT;
    float* s_v2 = sm + SM_V2;
    __shared__ int s_toff[98];

    const int tid = threadIdx.x;
    const int wid = tid >> 5, lane = tid & 31;
    const int tq = lane >> 2, cq = lane & 3;

    // zero smem (padded regions must stay finite/zero)
    for (int i = tid; i < SM1_FLOATS; i += NTHR1) sm[i] = 0.f;

    // window decode + per-token global offsets
    const int widx = blockIdx.x;
    const int b = widx >> 8;
    const int rr = widx & 255;
    const int dblk = rr >> 6, hblk = (rr >> 3) & 7, wblk = rr & 7;
    if (tid < 98) {
        int t = tid;
        int wd = (t >= 49);
        int rem = t - wd * 49;
        int wh = rem / 7, ww = rem - wh * 7;
        int d = dblk * 2 + wd, hh = hblk * 7 + wh, wg = wblk * 7 + ww;
        s_toff[t] = (((b * 8 + d) * 56 + hh) * 56 + wg) * 96;
    }
    __syncthreads();

    // ---- LN1 (one warp per token), write transposed [c][t] ----
    for (int t = wid; t < 98; t += NWARP1) {
        int off = s_toff[t];
        float v0 = x[off + lane];
        float v1 = x[off + lane + 32];
        float v2 = x[off + lane + 64];
        float s = v0 + v1 + v2;
#pragma unroll
        for (int o = 16; o; o >>= 1) s += __shfl_xor_sync(0xffffffffu, s, o);
        float mean = s * (1.f / 96.f);
        float d0 = v0 - mean, d1 = v1 - mean, d2 = v2 - mean;
        float q2 = d0 * d0 + d1 * d1 + d2 * d2;
#pragma unroll
        for (int o = 16; o; o >>= 1) q2 += __shfl_xor_sync(0xffffffffu, q2, o);
        float rstd = rsqrtf(q2 * (1.f / 96.f) + 1e-5f);
        s_xn[lane * TS + t]        = d0 * rstd * __ldg(&n1w[lane])      + __ldg(&n1b[lane]);
        s_xn[(lane + 32) * TS + t] = d1 * rstd * __ldg(&n1w[lane + 32]) + __ldg(&n1b[lane + 32]);
        s_xn[(lane + 64) * TS + t] = d2 * rstd * __ldg(&n1w[lane + 64]) + __ldg(&n1b[lane + 64]);
    }
    __syncthreads();

    // ---- QKV GEMM: M=98(->128) N=288 K=96 ----
    const float SCALE = 0.17677669529663687f;  // 1/sqrt(32)
    for (int tile = wid; tile < 72; tile += NWARP1) {
        int mt = tile & 3, nt = tile >> 2;
        int m0 = mt * 32, n0 = nt * 16;
        int am = m0 + tq * 4; if (am > 96) am = 96;
        int an = n0 + cq * 4;
        float acc[4][4] = {};
        gemm_tile<true>(s_xn, TS, g_qkvT, 288, 96, am, an, acc);
        int part = n0 / 96;  // 0=q 1=k 2=v (tiles never straddle)
#pragma unroll
        for (int i = 0; i < 4; ++i) {
            int t = m0 + tq * 4 + i;
            if (t < 98) {
#pragma unroll
                for (int j = 0; j < 4; ++j) {
                    int o = an + j;
                    float v = acc[i][j] + __ldg(&qkv_b[o]);
                    if (part == 0)      s_qk[o * TS + t] = v * SCALE;
                    else if (part == 1) s_qk[o * TS + t] = v;
                    else                s_v2[t * VS + (o - 192)] = v;
                }
            }
        }
    }
    __syncthreads();

    // ---- per-head attention ----
    for (int h = 0; h < NHEAD; ++h) {
        // S^T[m][n] = sum_d k[d][m] * q[d][n]   (q already scaled)
        for (int tile = wid; tile < 28; tile += NWARP1) {
            int mt = tile & 3, nt = tile >> 2;   // nt 0..6 -> n up to 112
            int m0 = mt * 32, n0 = nt * 16;
            int am = m0 + tq * 4; if (am > 96) am = 96;
            int an = n0 + cq * 4;
            float acc[4][4] = {};
            gemm_tile<false>(s_qk + (96 + h * 32) * TS, TS,
                             s_qk + (h * 32) * TS, TS, 32, am, an, acc);
#pragma unroll
            for (int i = 0; i < 4; ++i) {
                int m = m0 + tq * 4 + i;
                if (m < 98) {
#pragma unroll
                    for (int j = 0; j < 4; ++j)
                        s_at[m * AS + an + j] = acc[i][j];
                }
            }
        }
        __syncthreads();

        // softmax over m for each column n (+ relative position bias)
        const float* biash = g_bias + h * 98 * 98;
        for (int n = wid; n < 98; n += NWARP1) {
            int m3 = lane + 96;
            float v0 = s_at[lane * AS + n]        + __ldg(&biash[n * 98 + lane]);
            float v1 = s_at[(lane + 32) * AS + n] + __ldg(&biash[n * 98 + lane + 32]);
            float v2 = s_at[(lane + 64) * AS + n] + __ldg(&biash[n * 98 + lane + 64]);
            float v3 = (m3 < 98) ? s_at[m3 * AS + n] + __ldg(&biash[n * 98 + m3]) : -1e30f;
            float mx = fmaxf(fmaxf(v0, v1), fmaxf(v2, v3));
#pragma unroll
            for (int o = 16; o; o >>= 1) mx = fmaxf(mx, __shfl_xor_sync(0xffffffffu, mx, o));
            float e0 = __expf(v0 - mx), e1 = __expf(v1 - mx), e2 = __expf(v2 - mx);
            float e3 = (m3 < 98) ? __expf(v3 - mx) : 0.f;
            float ss = e0 + e1 + e2 + e3;
#pragma unroll
            for (int o = 16; o; o >>= 1) ss += __shfl_xor_sync(0xffffffffu, ss, o);
            float r = __fdividef(1.f, ss);
            s_at[lane * AS + n]        = e0 * r;
            s_at[(lane + 32) * AS + n] = e1 * r;
            s_at[(lane + 64) * AS + n] = e2 * r;
            if (m3 < 98) s_at[m3 * AS + n] = e3 * r;
        }
        __syncthreads();

        // out[n][d] = sum_m P^T[m][n] * v2[m][d] ; write transposed into s_xn [c][t]
        if (wid < 8) {
            int mt = wid & 3, nt = wid >> 2;
            int m0 = mt * 32;
            int am = m0 + tq * 4; if (am > 96) am = 96;
            int bn = h * 32 + nt * 16 + cq * 4;
            float acc[4][4] = {};
            gemm_tile<false>(s_at, AS, s_v2, VS, 98, am, bn, acc);
#pragma unroll
            for (int i = 0; i < 4; ++i) {
                int n = m0 + tq * 4 + i;
                if (n < 98) {
#pragma unroll
                    for (int j = 0; j < 4; ++j)
                        s_xn[(bn + j) * TS + n] = acc[i][j];
                }
            }
        }
        __syncthreads();
    }

    // ---- proj GEMM + residual -> g_xmid ----
    for (int tile = wid; tile < 24; tile += NWARP1) {
        int mt = tile & 3, nt = tile >> 2;
        int m0 = mt * 32, n0 = nt * 16;
        int am = m0 + tq * 4; if (am > 96) am = 96;
        int an = n0 + cq * 4;
        float acc[4][4] = {};
        gemm_tile<true>(s_xn, TS, g_projT, 96, 96, am, an, acc);
#pragma unroll
        for (int i = 0; i < 4; ++i) {
            int t = m0 + tq * 4 + i;
            if (t < 98) {
                int off = s_toff[t] + an;
                float4 xr = *reinterpret_cast<const float4*>(x + off);
                float4 o4;
                o4.x = acc[i][0] + __ldg(&proj_b[an + 0]) + xr.x;
                o4.y = acc[i][1] + __ldg(&proj_b[an + 1]) + xr.y;
                o4.z = acc[i][2] + __ldg(&proj_b[an + 2]) + xr.z;
                o4.w = acc[i][3] + __ldg(&proj_b[an + 3]) + xr.w;
                *reinterpret_cast<float4*>(&g_xmid[off]) = o4;
            }
        }
    }
}

// ---------------- kernel 2: LN2 + MLP + residual ----------------
__device__ __forceinline__ float gelu_exact(float v)
{
    return 0.5f * v * (1.f + erff(v * 0.70710678118654752f));
}

__global__ __launch_bounds__(NTHR2)
void mlp_kernel(const float* __restrict__ n2w, const float* __restrict__ n2b,
                const float* __restrict__ fc1_b, const float* __restrict__ fc2_b,
                float* __restrict__ out)
{
    extern __shared__ float sm[];
    float* s_x = sm + SM2_X;  // [96][TS2]
    float* s_h = sm + SM2_H;  // [384][TS2]
    const int tid = threadIdx.x;
    const int wid = tid >> 5, lane = tid & 31;
    const int tq = lane >> 2, cq = lane & 3;
    const int tbase = blockIdx.x * 32;

    // LN2 (warp per token), write transposed [c][t]
    for (int t = wid; t < 32; t += 8) {
        int off = (tbase + t) * 96;
        float v0 = g_xmid[off + lane];
        float v1 = g_xmid[off + lane + 32];
        float v2 = g_xmid[off + lane + 64];
        float s = v0 + v1 + v2;
#pragma unroll
        for (int o = 16; o; o >>= 1) s += __shfl_xor_sync(0xffffffffu, s, o);
        float mean = s * (1.f / 96.f);
        float d0 = v0 - mean, d1 = v1 - mean, d2 = v2 - mean;
        float q2 = d0 * d0 + d1 * d1 + d2 * d2;
#pragma unroll
        for (int o = 16; o; o >>= 1) q2 += __shfl_xor_sync(0xffffffffu, q2, o);
        float rstd = rsqrtf(q2 * (1.f / 96.f) + 1e-5f);
        s_x[lane * TS2 + t]        = d0 * rstd * __ldg(&n2w[lane])      + __ldg(&n2b[lane]);
        s_x[(lane + 32) * TS2 + t] = d1 * rstd * __ldg(&n2w[lane + 32]) + __ldg(&n2b[lane + 32]);
        s_x[(lane + 64) * TS2 + t] = d2 * rstd * __ldg(&n2w[lane + 64]) + __ldg(&n2b[lane + 64]);
    }
    __syncthreads();

    // fc1 + GELU: M=32 N=384 K=96, write h transposed [j][t]
    for (int tile = wid; tile < 24; tile += 8) {
        int n0 = tile * 16;
        int am = tq * 4;
        int an = n0 + cq * 4;
        float acc[4][4] = {};
        gemm_tile<true>(s_x, TS2, g_fc1T, 384, 96, am, an, acc);
#pragma unroll
        for (int j = 0; j < 4; ++j) {
            int o = an + j;
            float bb = __ldg(&fc1_b[o]);
            float4 hv;
            hv.x = gelu_exact(acc[0][j] + bb);
            hv.y = gelu_exact(acc[1][j] + bb);
            hv.z = gelu_exact(acc[2][j] + bb);
            hv.w = gelu_exact(acc[3][j] + bb);
            *reinterpret_cast<float4*>(&s_h[o * TS2 + am]) = hv;
        }
    }
    __syncthreads();

    // fc2 + residual: M=32 N=96 K=384
    if (wid < 6) {
        int n0 = wid * 16;
        int am = tq * 4;
        int an = n0 + cq * 4;
        float acc[4][4] = {};
        gemm_tile<true>(s_h, TS2, g_fc2T, 96, 384, am, an, acc);
#pragma unroll
        for (int i = 0; i < 4; ++i) {
            int off = (tbase + am + i) * 96 + an;
            float4 xr = *reinterpret_cast<const float4*>(&g_xmid[off]);
            float4 o4;
            o4.x = acc[i][0] + __ldg(&fc2_b[an + 0]) + xr.x;
            o4.y = acc[i][1] + __ldg(&fc2_b[an + 1]) + xr.y;
            o4.z = acc[i][2] + __ldg(&fc2_b[an + 2]) + xr.z;
            o4.w = acc[i][3] + __ldg(&fc2_b[an + 3]) + xr.w;
            *reinterpret_cast<float4*>(&out[off]) = o4;
        }
    }
}

// ---------------- launch ----------------
extern "C" void kernel_launch(void* const* d_in, const int* in_sizes, int n_in,
                              void* d_out, int out_size)
{
    const float* x      = (const float*)d_in[0];
    const float* n1w    = (const float*)d_in[1];
    const float* n1b    = (const float*)d_in[2];
    const float* qkv_w  = (const float*)d_in[3];
    const float* qkv_b  = (const float*)d_in[4];
    const float* proj_w = (const float*)d_in[5];
    const float* proj_b = (const float*)d_in[6];
    const float* rpb    = (const float*)d_in[7];
    const float* n2w    = (const float*)d_in[8];
    const float* n2b    = (const float*)d_in[9];
    const float* fc1_b  = (const float*)d_in[11];
    const float* fc1_w  = (const float*)d_in[10];
    const float* fc2_w  = (const float*)d_in[12];
    const float* fc2_b  = (const float*)d_in[13];
    float* out = (float*)d_out;

    cudaFuncSetAttribute(attn_kernel, cudaFuncAttributeMaxDynamicSharedMemorySize, SM1_FLOATS * 4);
    cudaFuncSetAttribute(mlp_kernel,  cudaFuncAttributeMaxDynamicSharedMemorySize, SM2_FLOATS * 4);

    prep_kernel<<<96, 256>>>(qkv_w, proj_w, fc1_w, fc2_w, rpb);
    attn_kernel<<<NWIN, NTHR1, SM1_FLOATS * 4>>>(x, n1w, n1b, qkv_b, proj_b);
    mlp_kernel<<<NTOKENS / 32, NTHR2, SM2_FLOATS * 4>>>(n2w, n2b, fc1_b, fc2_b, out);
}

// round 2
// speedup vs baseline: 2.9831x; 2.9831x over previous
#include <cuda_runtime.h>
#include <math.h>

#define NWIN    2048
#define NTOKENS 200704
#define XELEMS  (NTOKENS * 96)
#define SCALE   0.17677669529663687f   // 1/sqrt(32)

// ---------------- device scratch ----------------
__device__ float g_xmid[XELEMS];
__device__ float g_bias[3 * 98 * 98];   // [h][query i][key j]

// ---------------- prep: bias table only ----------------
__global__ void prep_kernel(const float* __restrict__ rpb)
{
    int tid = blockIdx.x * blockDim.x + threadIdx.x;
    int stride = gridDim.x * blockDim.x;
    for (int idx = tid; idx < 3 * 98 * 98; idx += stride) {
        int h = idx / (98 * 98);
        int r = idx - h * 98 * 98;
        int n = r / 98, m = r - n * 98;
        int nd = n / 49, nh = (n % 49) / 7, nw = n % 7;
        int md = m / 49, mh = (m % 49) / 7, mw = m % 7;
        int rel = (nd - md + 1) * 169 + (nh - mh + 6) * 13 + (nw - mw + 6);
        g_bias[idx] = rpb[rel * 3 + h];
    }
}

// ---------------- tf32 warp MMA ----------------
__device__ __forceinline__ void mma8(float* c,
                                     unsigned a0, unsigned a1, unsigned a2, unsigned a3,
                                     unsigned b0, unsigned b1)
{
    asm volatile(
        "mma.sync.aligned.m16n8k8.row.col.f32.tf32.tf32.f32 "
        "{%0,%1,%2,%3}, {%4,%5,%6,%7}, {%8,%9}, {%0,%1,%2,%3};\n"
        : "+f"(c[0]), "+f"(c[1]), "+f"(c[2]), "+f"(c[3])
        : "r"(a0), "r"(a1), "r"(a2), "r"(a3), "r"(b0), "r"(b1));
}

// 16x16 macro-tile (two n-tiles of 8). A row-major [m][k], B col-major [n][k].
template <int K, int LDA, int LDB>
__device__ __forceinline__ void gemm16x16(const float* __restrict__ As,
                                          const float* __restrict__ Bs,
                                          int m0, int n0, int g, int t4,
                                          float c0[4], float c1[4])
{
    const float* Ap  = As + (m0 + g) * LDA + t4;
    const float* Bp0 = Bs + (n0 + g) * LDB + t4;
    const float* Bp1 = Bp0 + 8 * LDB;
#pragma unroll 4
    for (int k = 0; k < K; k += 8) {
        unsigned a0  = __float_as_uint(Ap[k]);
        unsigned a1  = __float_as_uint(Ap[8 * LDA + k]);
        unsigned a2  = __float_as_uint(Ap[k + 4]);
        unsigned a3  = __float_as_uint(Ap[8 * LDA + k + 4]);
        unsigned b00 = __float_as_uint(Bp0[k]);
        unsigned b01 = __float_as_uint(Bp0[k + 4]);
        unsigned b10 = __float_as_uint(Bp1[k]);
        unsigned b11 = __float_as_uint(Bp1[k + 4]);
        mma8(c0, a0, a1, a2, a3, b00, b01);
        mma8(c1, a0, a1, a2, a3, b10, b11);
    }
}

// ---------------- kernel 1: LN1 + QKV + attention + proj + residual ----------------
// smem (floats): XN [112][100]  @0      (11200)
//                S  [112][116]  @11200  (12992)
//                QH [112][36]   @24192  (4032)
//                KH [112][36]   @28224  (4032)
//                VH [32][116]   @32256  (3712)
//                WQ [96][100]   @35968  (9600)
//                WP [96][36]    @45568  (3456)
//                AO [112][36]   @49024  (4032)
#define SM1_FLOATS 53056

__global__ __launch_bounds__(512)
void attn_kernel(const float* __restrict__ x,
                 const float* __restrict__ n1w, const float* __restrict__ n1b,
                 const float* __restrict__ qkv_w, const float* __restrict__ qkv_b,
                 const float* __restrict__ proj_w, const float* __restrict__ proj_b)
{
    extern __shared__ float sm[];
    float* XN = sm;
    float* S  = sm + 11200;
    float* QH = sm + 24192;
    float* KH = sm + 28224;
    float* VH = sm + 32256;
    float* WQ = sm + 35968;
    float* WP = sm + 45568;
    float* AO = sm + 49024;
    __shared__ int s_toff[98];

    const int tid = threadIdx.x;
    const int wid = tid >> 5, lane = tid & 31;
    const int g = lane >> 2, t4 = lane & 3;

    // window decode
    const int widx = blockIdx.x;
    const int b = widx >> 8;
    const int rr = widx & 255;
    const int dblk = rr >> 6, hblk = (rr >> 3) & 7, wblk = rr & 7;
    if (tid < 98) {
        int wd = (tid >= 49);
        int rem = tid - wd * 49;
        int wh = rem / 7, ww = rem - wh * 7;
        s_toff[tid] = (((b * 8 + dblk * 2 + wd) * 56 + hblk * 7 + wh) * 56 + wblk * 7 + ww) * 96;
    }
    // zero XN pad rows 98..111
    for (int i = tid; i < 14 * 100; i += 512) XN[9800 + i] = 0.f;
    __syncthreads();

    // ---- LN1 -> XN row-major [t][c], stride 100 ----
    for (int t = wid; t < 98; t += 16) {
        int off = s_toff[t];
        float v0 = x[off + lane];
        float v1 = x[off + lane + 32];
        float v2 = x[off + lane + 64];
        float s = v0 + v1 + v2;
#pragma unroll
        for (int o = 16; o; o >>= 1) s += __shfl_xor_sync(0xffffffffu, s, o);
        float mean = s * (1.f / 96.f);
        float d0 = v0 - mean, d1 = v1 - mean, d2 = v2 - mean;
        float q2 = d0 * d0 + d1 * d1 + d2 * d2;
#pragma unroll
        for (int o = 16; o; o >>= 1) q2 += __shfl_xor_sync(0xffffffffu, q2, o);
        float rstd = rsqrtf(q2 * (1.f / 96.f) + 1e-5f);
        XN[t * 100 + lane]      = d0 * rstd * __ldg(&n1w[lane])      + __ldg(&n1b[lane]);
        XN[t * 100 + lane + 32] = d1 * rstd * __ldg(&n1w[lane + 32]) + __ldg(&n1b[lane + 32]);
        XN[t * 100 + lane + 64] = d2 * rstd * __ldg(&n1w[lane + 64]) + __ldg(&n1b[lane + 64]);
    }

    float cp[3][2][4] = {};   // persistent proj accumulators

    for (int h = 0; h < 3; ++h) {
        __syncthreads();   // XN ready / previous head's WQ-WP consumers done

        // ---- stage per-head weights: WQ rows 0-31 q, 32-63 k, 64-95 v; WP proj slice ----
        for (int idx = tid; idx < 96 * 24; idx += 512) {
            int r = idx / 24, q4 = idx % 24;
            int part = r >> 5, d = r & 31;
            int o = part * 96 + h * 32 + d;
            *reinterpret_cast<float4*>(&WQ[r * 100 + q4 * 4]) =
                *reinterpret_cast<const float4*>(&qkv_w[o * 96 + q4 * 4]);
        }
        for (int idx = tid; idx < 96 * 8; idx += 512) {
            int o = idx >> 3, q4 = idx & 7;
            *reinterpret_cast<float4*>(&WP[o * 36 + q4 * 4]) =
                *reinterpret_cast<const float4*>(&proj_w[o * 96 + h * 32 + q4 * 4]);
        }
        __syncthreads();

        // ---- QKV for this head: C[112 x 96] ----
        for (int mac = wid; mac < 42; mac += 16) {
            int mt = mac / 6, nt = mac % 6;
            int m0 = mt * 16, n0 = nt * 16;
            float c0[4] = {}, c1[4] = {};
            gemm16x16<96, 100, 100>(XN, WQ, m0, n0, g, t4, c0, c1);
            int part = n0 >> 5;
#pragma unroll
            for (int half = 0; half < 2; ++half) {
                float* cc = half ? c1 : c0;
                int colb = n0 + half * 8 + 2 * t4;
                int d = colb & 31;
                int o = part * 96 + h * 32 + d;
                float b0 = __ldg(&qkv_b[o]), b1 = __ldg(&qkv_b[o + 1]);
#pragma unroll
                for (int rh = 0; rh < 2; ++rh) {
                    int trow = m0 + g + rh * 8;
                    float v0 = cc[rh * 2 + 0] + b0;
                    float v1 = cc[rh * 2 + 1] + b1;
                    if (trow >= 98) { v0 = 0.f; v1 = 0.f; }   // clean pads
                    if (part == 0) {
                        *reinterpret_cast<float2*>(&QH[trow * 36 + d]) =
                            make_float2(v0 * SCALE, v1 * SCALE);
                    } else if (part == 1) {
                        *reinterpret_cast<float2*>(&KH[trow * 36 + d]) = make_float2(v0, v1);
                    } else {
                        VH[d * 116 + trow]       = v0;
                        VH[(d + 1) * 116 + trow] = v1;
                    }
                }
            }
        }
        __syncthreads();

        // ---- S = Q K^T : C[112 x 112] ----
        for (int mac = wid; mac < 49; mac += 16) {
            int mt = mac / 7, nt = mac % 7;
            int m0 = mt * 16, n0 = nt * 16;
            float c0[4] = {}, c1[4] = {};
            gemm16x16<32, 36, 36>(QH, KH, m0, n0, g, t4, c0, c1);
#pragma unroll
            for (int half = 0; half < 2; ++half) {
                float* cc = half ? c1 : c0;
                int col = n0 + half * 8 + 2 * t4;
#pragma unroll
                for (int rh = 0; rh < 2; ++rh)
                    *reinterpret_cast<float2*>(&S[(m0 + g + rh * 8) * 116 + col]) =
                        make_float2(cc[rh * 2], cc[rh * 2 + 1]);
            }
        }
        __syncthreads();

        // ---- softmax rows (query i), + bias ----
        {
            const float* biash = g_bias + h * 98 * 98;
            for (int i = wid; i < 98; i += 16) {
                float* row = S + i * 116;
                const float* brow = biash + i * 98;
                float v0 = row[lane]      + __ldg(&brow[lane]);
                float v1 = row[lane + 32] + __ldg(&brow[lane + 32]);
                float v2 = row[lane + 64] + __ldg(&brow[lane + 64]);
                bool ok3 = (lane < 2);
                float v3 = ok3 ? row[lane + 96] + __ldg(&brow[lane + 96]) : -1e30f;
                float mx = fmaxf(fmaxf(v0, v1), fmaxf(v2, v3));
#pragma unroll
                for (int o = 16; o; o >>= 1) mx = fmaxf(mx, __shfl_xor_sync(0xffffffffu, mx, o));
                float e0 = __expf(v0 - mx), e1 = __expf(v1 - mx), e2 = __expf(v2 - mx);
                float e3 = ok3 ? __expf(v3 - mx) : 0.f;
                float ss = e0 + e1 + e2 + e3;
#pragma unroll
                for (int o = 16; o; o >>= 1) ss += __shfl_xor_sync(0xffffffffu, ss, o);
                float r = __fdividef(1.f, ss);
                row[lane]      = e0 * r;
                row[lane + 32] = e1 * r;
                row[lane + 64] = e2 * r;
                if (ok3) row[lane + 96] = e3 * r;
            }
        }
        __syncthreads();

        // ---- PV: AO[112 x 32] = P[112 x 112] * V ----
        if (wid < 14) {
            int mt = wid >> 1, nt = wid & 1;
            int m0 = mt * 16, n0 = nt * 16;
            float c0[4] = {}, c1[4] = {};
            gemm16x16<112, 116, 116>(S, VH, m0, n0, g, t4, c0, c1);
#pragma unroll
            for (int half = 0; half < 2; ++half) {
                float* cc = half ? c1 : c0;
                int col = n0 + half * 8 + 2 * t4;
#pragma unroll
                for (int rh = 0; rh < 2; ++rh)
                    *reinterpret_cast<float2*>(&AO[(m0 + g + rh * 8) * 36 + col]) =
                        make_float2(cc[rh * 2], cc[rh * 2 + 1]);
            }
        }
        __syncthreads();

        // ---- proj accumulate: C[112 x 96] += AO * WP ----
#pragma unroll
        for (int i = 0; i < 3; ++i) {
            int mac = wid + 16 * i;
            if (mac < 42) {
                int mt = mac / 6, nt = mac % 6;
                gemm16x16<32, 36, 36>(AO, WP, mt * 16, nt * 16, g, t4, cp[i][0], cp[i][1]);
            }
        }
    }

    // ---- epilogue: bias + residual -> g_xmid ----
#pragma unroll
    for (int i = 0; i < 3; ++i) {
        int mac = wid + 16 * i;
        if (mac < 42) {
            int mt = mac / 6, nt = mac % 6;
            int m0 = mt * 16, n0 = nt * 16;
#pragma unroll
            for (int half = 0; half < 2; ++half) {
                int col = n0 + half * 8 + 2 * t4;
                float pb0 = __ldg(&proj_b[col]), pb1 = __ldg(&proj_b[col + 1]);
#pragma unroll
                for (int rh = 0; rh < 2; ++rh) {
                    int trow = m0 + g + rh * 8;
                    if (trow < 98) {
                        int off = s_toff[trow] + col;
                        float2 xr = *reinterpret_cast<const float2*>(&x[off]);
                        float2 o2;
                        o2.x = cp[i][half][rh * 2]     + pb0 + xr.x;
                        o2.y = cp[i][half][rh * 2 + 1] + pb1 + xr.y;
                        *reinterpret_cast<float2*>(&g_xmid[off]) = o2;
                    }
                }
            }
        }
    }
}

// ---------------- kernel 2: LN2 + MLP + residual ----------------
// smem: X [128][100] @0 (12800), H [128][100] @12800, W1 [96][100] @25600, W2 [96][100] @35200
#define SM2_FLOATS 44800

__device__ __forceinline__ float gelu_exact(float v)
{
    return 0.5f * v * (1.f + erff(v * 0.70710678118654752f));
}

__global__ __launch_bounds__(512)
void mlp_kernel(const float* __restrict__ n2w, const float* __restrict__ n2b,
                const float* __restrict__ fc1_w, const float* __restrict__ fc1_b,
                const float* __restrict__ fc2_w, const float* __restrict__ fc2_b,
                float* __restrict__ out)
{
    extern __shared__ float sm[];
    float* X  = sm;
    float* H  = sm + 12800;
    float* W1 = sm + 25600;
    float* W2 = sm + 35200;

    const int tid = threadIdx.x;
    const int wid = tid >> 5, lane = tid & 31;
    const int g = lane >> 2, t4 = lane & 3;
    const int tbase = blockIdx.x * 128;

    // ---- LN2 -> X [t][c] ----
    for (int t = wid; t < 128; t += 16) {
        const float* p = g_xmid + (tbase + t) * 96;
        float v0 = p[lane], v1 = p[lane + 32], v2 = p[lane + 64];
        float s = v0 + v1 + v2;
#pragma unroll
        for (int o = 16; o; o >>= 1) s += __shfl_xor_sync(0xffffffffu, s, o);
        float mean = s * (1.f / 96.f);
        float d0 = v0 - mean, d1 = v1 - mean, d2 = v2 - mean;
        float q2 = d0 * d0 + d1 * d1 + d2 * d2;
#pragma unroll
        for (int o = 16; o; o >>= 1) q2 += __shfl_xor_sync(0xffffffffu, q2, o);
        float rstd = rsqrtf(q2 * (1.f / 96.f) + 1e-5f);
        X[t * 100 + lane]      = d0 * rstd * __ldg(&n2w[lane])      + __ldg(&n2b[lane]);
        X[t * 100 + lane + 32] = d1 * rstd * __ldg(&n2w[lane + 32]) + __ldg(&n2b[lane + 32]);
        X[t * 100 + lane + 64] = d2 * rstd * __ldg(&n2w[lane + 64]) + __ldg(&n2b[lane + 64]);
    }

    float c2[3][2][4] = {};   // persistent fc2 accumulators

    for (int ch = 0; ch < 4; ++ch) {
        __syncthreads();   // X ready / previous chunk's H-W2 consumers done
        // stage weight chunks
        for (int idx = tid; idx < 96 * 24; idx += 512) {
            int r = idx / 24, q4 = idx % 24;
            *reinterpret_cast<float4*>(&W1[r * 100 + q4 * 4]) =
                *reinterpret_cast<const float4*>(&fc1_w[(ch * 96 + r) * 96 + q4 * 4]);
            *reinterpret_cast<float4*>(&W2[r * 100 + q4 * 4]) =
                *reinterpret_cast<const float4*>(&fc2_w[r * 384 + ch * 96 + q4 * 4]);
        }
        __syncthreads();

        // fc1 chunk + GELU -> H
#pragma unroll
        for (int i = 0; i < 3; ++i) {
            int mac = wid + 16 * i;     // 48 macros: 8m x 6n
            int mt = mac / 6, nt = mac % 6;
            int m0 = mt * 16, n0 = nt * 16;
            float c0[4] = {}, c1[4] = {};
            gemm16x16<96, 100, 100>(X, W1, m0, n0, g, t4, c0, c1);
#pragma unroll
            for (int half = 0; half < 2; ++half) {
                float* cc = half ? c1 : c0;
                int col = n0 + half * 8 + 2 * t4;
                float b0 = __ldg(&fc1_b[ch * 96 + col]);
                float b1 = __ldg(&fc1_b[ch * 96 + col + 1]);
#pragma unroll
                for (int rh = 0; rh < 2; ++rh) {
                    float2 hv;
                    hv.x = gelu_exact(cc[rh * 2]     + b0);
                    hv.y = gelu_exact(cc[rh * 2 + 1] + b1);
                    *reinterpret_cast<float2*>(&H[(m0 + g + rh * 8) * 100 + col]) = hv;
                }
            }
        }
        __syncthreads();

        // fc2 chunk accumulate
#pragma unroll
        for (int i = 0; i < 3; ++i) {
            int mac = wid + 16 * i;
            int mt = mac / 6, nt = mac % 6;
            gemm16x16<96, 100, 100>(H, W2, mt * 16, nt * 16, g, t4, c2[i][0], c2[i][1]);
        }
    }

    // ---- epilogue: bias + residual -> out ----
#pragma unroll
    for (int i = 0; i < 3; ++i) {
        int mac = wid + 16 * i;
        int mt = mac / 6, nt = mac % 6;
        int m0 = mt * 16, n0 = nt * 16;
#pragma unroll
        for (int half = 0; half < 2; ++half) {
            int col = n0 + half * 8 + 2 * t4;
            float b0 = __ldg(&fc2_b[col]), b1 = __ldg(&fc2_b[col + 1]);
#pragma unroll
            for (int rh = 0; rh < 2; ++rh) {
                int trow = m0 + g + rh * 8;
                int off = (tbase + trow) * 96 + col;
                float2 xr = *reinterpret_cast<const float2*>(&g_xmid[off]);
                float2 o2;
                o2.x = c2[i][half][rh * 2]     + b0 + xr.x;
                o2.y = c2[i][half][rh * 2 + 1] + b1 + xr.y;
                *reinterpret_cast<float2*>(&out[off]) = o2;
            }
        }
    }
}

// ---------------- launch ----------------
extern "C" void kernel_launch(void* const* d_in, const int* in_sizes, int n_in,
                              void* d_out, int out_size)
{
    const float* x      = (const float*)d_in[0];
    const float* n1w    = (const float*)d_in[1];
    const float* n1b    = (const float*)d_in[2];
    const float* qkv_w  = (const float*)d_in[3];
    const float* qkv_b  = (const float*)d_in[4];
    const float* proj_w = (const float*)d_in[5];
    const float* proj_b = (const float*)d_in[6];
    const float* rpb    = (const float*)d_in[7];
    const float* n2w    = (const float*)d_in[8];
    const float* n2b    = (const float*)d_in[9];
    const float* fc1_w  = (const float*)d_in[10];
    const float* fc1_b  = (const float*)d_in[11];
    const float* fc2_w  = (const float*)d_in[12];
    const float* fc2_b  = (const float*)d_in[13];
    float* out = (float*)d_out;

    cudaFuncSetAttribute(attn_kernel, cudaFuncAttributeMaxDynamicSharedMemorySize, SM1_FLOATS * 4);
    cudaFuncSetAttribute(mlp_kernel,  cudaFuncAttributeMaxDynamicSharedMemorySize, SM2_FLOATS * 4);

    prep_kernel<<<64, 256>>>(rpb);
    attn_kernel<<<NWIN, 512, SM1_FLOATS * 4>>>(x, n1w, n1b, qkv_w, qkv_b, proj_w, proj_b);
    mlp_kernel<<<NTOKENS / 128, 512, SM2_FLOATS * 4>>>(n2w, n2b, fc1_w, fc1_b, fc2_w, fc2_b, out);
}

// round 3
// speedup vs baseline: 4.3434x; 1.4560x over previous
#include <cuda_runtime.h>
#include <cuda_bf16.h>
#include <math.h>

#define NWIN    2048
#define NTOKENS 200704
#define XELEMS  (NTOKENS * 96)
#define SCALE   0.17677669529663687f   // 1/sqrt(32)

// ---------------- device scratch ----------------
__device__ float g_xmid[XELEMS];
__device__ __nv_bfloat16 g_bias_bf[3 * 98 * 98];  // [h][i][j]
__device__ __nv_bfloat16 g_wqkv[288 * 96];
__device__ __nv_bfloat16 g_wproj[96 * 96];
__device__ __nv_bfloat16 g_fc1[384 * 96];
__device__ __nv_bfloat16 g_fc2[96 * 384];

// ---------------- prep: bf16 weights + bias table ----------------
__global__ void prep_kernel(const float* __restrict__ qkv_w,
                            const float* __restrict__ proj_w,
                            const float* __restrict__ fc1_w,
                            const float* __restrict__ fc2_w,
                            const float* __restrict__ rpb)
{
    int tid = blockIdx.x * blockDim.x + threadIdx.x;
    int stride = gridDim.x * blockDim.x;
    for (int i = tid; i < 288 * 96; i += stride) g_wqkv[i]  = __float2bfloat16_rn(qkv_w[i]);
    for (int i = tid; i < 96 * 96;  i += stride) g_wproj[i] = __float2bfloat16_rn(proj_w[i]);
    for (int i = tid; i < 384 * 96; i += stride) g_fc1[i]   = __float2bfloat16_rn(fc1_w[i]);
    for (int i = tid; i < 96 * 384; i += stride) g_fc2[i]   = __float2bfloat16_rn(fc2_w[i]);
    for (int idx = tid; idx < 3 * 98 * 98; idx += stride) {
        int h = idx / (98 * 98);
        int r = idx - h * 98 * 98;
        int n = r / 98, m = r - n * 98;
        int nd = n / 49, nh = (n % 49) / 7, nw = n % 7;
        int md = m / 49, mh = (m % 49) / 7, mw = m % 7;
        int rel = (nd - md + 1) * 169 + (nh - mh + 6) * 13 + (nw - mw + 6);
        g_bias_bf[idx] = __float2bfloat16_rn(rpb[rel * 3 + h]);
    }
}

// ---------------- MMA building blocks ----------------
__device__ __forceinline__ unsigned sm_u32(const void* p)
{
    return (unsigned)__cvta_generic_to_shared(p);
}

__device__ __forceinline__ void ldsm4(unsigned addr, unsigned& r0, unsigned& r1,
                                      unsigned& r2, unsigned& r3)
{
    asm volatile("ldmatrix.sync.aligned.m8n8.x4.shared.b16 {%0,%1,%2,%3}, [%4];\n"
                 : "=r"(r0), "=r"(r1), "=r"(r2), "=r"(r3) : "r"(addr));
}

__device__ __forceinline__ void ldsm4t(unsigned addr, unsigned& r0, unsigned& r1,
                                       unsigned& r2, unsigned& r3)
{
    asm volatile("ldmatrix.sync.aligned.m8n8.x4.trans.shared.b16 {%0,%1,%2,%3}, [%4];\n"
                 : "=r"(r0), "=r"(r1), "=r"(r2), "=r"(r3) : "r"(addr));
}

__device__ __forceinline__ void mmabf(float* c, unsigned a0, unsigned a1, unsigned a2,
                                      unsigned a3, unsigned b0, unsigned b1)
{
    asm volatile(
        "mma.sync.aligned.m16n8k16.row.col.f32.bf16.bf16.f32 "
        "{%0,%1,%2,%3}, {%4,%5,%6,%7}, {%8,%9}, {%0,%1,%2,%3};\n"
        : "+f"(c[0]), "+f"(c[1]), "+f"(c[2]), "+f"(c[3])
        : "r"(a0), "r"(a1), "r"(a2), "r"(a3), "r"(b0), "r"(b1));
}

// 16x16 macro-tile. A row-major [m][k]; B either [n][k] row-major (BT=false)
// or natural [k][n] row-major loaded via ldmatrix.trans (BT=true).
template <int KSTEPS, int LDA, int LDB, bool BT>
__device__ __forceinline__ void gemm16(const __nv_bfloat16* __restrict__ A,
                                       const __nv_bfloat16* __restrict__ B,
                                       int m0, int n0, int lane,
                                       float c0[4], float c1[4])
{
    const int l7 = lane & 7;
    const int rowA = m0 + ((lane >> 3) & 1) * 8 + l7;
    const int kA   = ((lane >> 4) & 1) * 8;
    unsigned aA = sm_u32(A + rowA * LDA + kA);
    unsigned aB;
    if (!BT) {
        int rowB = n0 + ((lane >> 4) & 1) * 8 + l7;
        int kB   = ((lane >> 3) & 1) * 8;
        aB = sm_u32(B + rowB * LDB + kB);
    } else {
        int rowB = ((lane >> 3) & 1) * 8 + l7;          // k-row
        int colB = n0 + ((lane >> 4) & 1) * 8;
        aB = sm_u32(B + rowB * LDB + colB);
    }
#pragma unroll
    for (int ks = 0; ks < KSTEPS; ++ks) {
        unsigned a0, a1, a2, a3, b0, b1, b2, b3;
        ldsm4(aA + ks * 32, a0, a1, a2, a3);
        if (!BT) ldsm4(aB + ks * 32, b0, b1, b2, b3);
        else     ldsm4t(aB + ks * 16 * LDB * 2, b0, b1, b2, b3);
        mmabf(c0, a0, a1, a2, a3, b0, b1);
        mmabf(c1, a0, a1, a2, a3, b2, b3);
    }
}

__device__ __forceinline__ void st_bf2(__nv_bfloat16* p, float x, float y)
{
    __nv_bfloat162 v;
    v.x = __float2bfloat16_rn(x);
    v.y = __float2bfloat16_rn(y);
    *reinterpret_cast<__nv_bfloat162*>(p) = v;
}

// ---------------- kernel 1 smem layout (bytes) ----------------
#define A_XN 0           // bf16 [112][104] = 23296   (reused as Wproj [96][104])
#define A_SW 23296       // Wqkv bf16 [288][104] = 59904; later S fp32 [112][116] = 51968
#define A_Q  83200       // bf16 [112][104]
#define A_K  106496      // bf16 [112][104]
#define A_V  129792      // bf16 [112][104]
#define A_P  153088      // bf16 [112][120] = 26880
#define A_AO 179968      // bf16 [112][104]
#define SM1_BYTES 203264

__global__ __launch_bounds__(512)
void attn_kernel(const float* __restrict__ x,
                 const float* __restrict__ n1w, const float* __restrict__ n1b,
                 const float* __restrict__ qkv_b, const float* __restrict__ proj_b)
{
    extern __shared__ char smc[];
    __nv_bfloat16* XN = (__nv_bfloat16*)(smc + A_XN);
    float*         S  = (float*)(smc + A_SW);
    __nv_bfloat16* WK = (__nv_bfloat16*)(smc + A_SW);
    __nv_bfloat16* Q  = (__nv_bfloat16*)(smc + A_Q);
    __nv_bfloat16* K  = (__nv_bfloat16*)(smc + A_K);
    __nv_bfloat16* V  = (__nv_bfloat16*)(smc + A_V);
    __nv_bfloat16* P  = (__nv_bfloat16*)(smc + A_P);
    __nv_bfloat16* AO = (__nv_bfloat16*)(smc + A_AO);
    __nv_bfloat16* WP = (__nv_bfloat16*)(smc + A_XN);
    __shared__ int s_toff[98];

    const int tid = threadIdx.x;
    const int wid = tid >> 5, lane = tid & 31;
    const int g = lane >> 2, t4 = lane & 3;

    // window decode
    const int widx = blockIdx.x;
    const int b = widx >> 8;
    const int rr = widx & 255;
    const int dblk = rr >> 6, hblk = (rr >> 3) & 7, wblk = rr & 7;
    if (tid < 98) {
        int wd = (tid >= 49);
        int rem = tid - wd * 49;
        int wh = rem / 7, ww = rem - wh * 7;
        s_toff[tid] = (((b * 8 + dblk * 2 + wd) * 56 + hblk * 7 + wh) * 56 + wblk * 7 + ww) * 96;
    }
    // zero XN pad rows 98..111 and all of P
    for (int i = tid; i < 14 * 104; i += 512) XN[98 * 104 + i] = __float2bfloat16_rn(0.f);
    for (int i = tid; i < 112 * 120 / 2; i += 512) reinterpret_cast<unsigned*>(P)[i] = 0u;

    // stage Wqkv: 288 rows x 96 bf16 -> stride 104
    for (int idx = tid; idx < 288 * 12; idx += 512) {
        int r = idx / 12, q = idx % 12;
        *reinterpret_cast<uint4*>(WK + r * 104 + q * 8) =
            *reinterpret_cast<const uint4*>(g_wqkv + r * 96 + q * 8);
    }

    // ---- LN1 -> XN bf16 [t][c] ----
    for (int t = wid; t < 98; t += 16) {
        int off = s_toff[t];
        float v0 = x[off + lane];
        float v1 = x[off + lane + 32];
        float v2 = x[off + lane + 64];
        float s = v0 + v1 + v2;
#pragma unroll
        for (int o = 16; o; o >>= 1) s += __shfl_xor_sync(0xffffffffu, s, o);
        float mean = s * (1.f / 96.f);
        float d0 = v0 - mean, d1 = v1 - mean, d2 = v2 - mean;
        float q2 = d0 * d0 + d1 * d1 + d2 * d2;
#pragma unroll
        for (int o = 16; o; o >>= 1) q2 += __shfl_xor_sync(0xffffffffu, q2, o);
        float rstd = rsqrtf(q2 * (1.f / 96.f) + 1e-5f);
        XN[t * 104 + lane] =
            __float2bfloat16_rn(d0 * rstd * __ldg(&n1w[lane]) + __ldg(&n1b[lane]));
        XN[t * 104 + lane + 32] =
            __float2bfloat16_rn(d1 * rstd * __ldg(&n1w[lane + 32]) + __ldg(&n1b[lane + 32]));
        XN[t * 104 + lane + 64] =
            __float2bfloat16_rn(d2 * rstd * __ldg(&n1w[lane + 64]) + __ldg(&n1b[lane + 64]));
    }
    __syncthreads();

    // ---- QKV (all heads): C[112 x 288] ----
    for (int mac = wid; mac < 126; mac += 16) {
        int mt = mac / 18, nt = mac % 18;
        int m0 = mt * 16, n0 = nt * 16;
        float c0[4] = {}, c1[4] = {};
        gemm16<6, 104, 104, false>(XN, WK, m0, n0, lane, c0, c1);
        int part = n0 / 96;                // 0=q 1=k 2=v (tiles never straddle)
#pragma unroll
        for (int half = 0; half < 2; ++half) {
            float* cc = half ? c1 : c0;
            int ocol = n0 + half * 8 + 2 * t4;
            int d = ocol - part * 96;
            float b0 = __ldg(&qkv_b[ocol]), b1 = __ldg(&qkv_b[ocol + 1]);
#pragma unroll
            for (int rh = 0; rh < 2; ++rh) {
                int trow = m0 + g + rh * 8;
                float v0 = cc[rh * 2]     + b0;
                float v1 = cc[rh * 2 + 1] + b1;
                if (trow >= 98) { v0 = 0.f; v1 = 0.f; }
                if (part == 0)      st_bf2(Q + trow * 104 + d, v0 * SCALE, v1 * SCALE);
                else if (part == 1) st_bf2(K + trow * 104 + d, v0, v1);
                else                st_bf2(V + trow * 104 + d, v0, v1);
            }
        }
    }
    __syncthreads();

    // stage Wproj into XN space (XN dead from here on)
    for (int idx = tid; idx < 96 * 12; idx += 512) {
        int r = idx / 12, q = idx % 12;
        *reinterpret_cast<uint4*>(WP + r * 104 + q * 8) =
            *reinterpret_cast<const uint4*>(g_wproj + r * 96 + q * 8);
    }

    // ---- per-head attention ----
    for (int h = 0; h < 3; ++h) {
        // S = Q_h K_h^T : C[112 x 112] fp32
        for (int mac = wid; mac < 49; mac += 16) {
            int mt = mac / 7, nt = mac % 7;
            int m0 = mt * 16, n0 = nt * 16;
            float c0[4] = {}, c1[4] = {};
            gemm16<2, 104, 104, false>(Q + h * 32, K + h * 32, m0, n0, lane, c0, c1);
#pragma unroll
            for (int half = 0; half < 2; ++half) {
                float* cc = half ? c1 : c0;
                int col = n0 + half * 8 + 2 * t4;
#pragma unroll
                for (int rh = 0; rh < 2; ++rh)
                    *reinterpret_cast<float2*>(&S[(m0 + g + rh * 8) * 116 + col]) =
                        make_float2(cc[rh * 2], cc[rh * 2 + 1]);
            }
        }
        __syncthreads();

        // softmax rows + bias -> P bf16
        {
            const __nv_bfloat16* biash = g_bias_bf + h * 98 * 98;
            for (int i = wid; i < 98; i += 16) {
                float* row = S + i * 116;
                const __nv_bfloat16* brow = biash + i * 98;
                float v0 = row[lane]      + __bfloat162float(brow[lane]);
                float v1 = row[lane + 32] + __bfloat162float(brow[lane + 32]);
                float v2 = row[lane + 64] + __bfloat162float(brow[lane + 64]);
                bool ok3 = (lane < 2);
                float v3 = ok3 ? row[lane + 96] + __bfloat162float(brow[lane + 96]) : -1e30f;
                float mx = fmaxf(fmaxf(v0, v1), fmaxf(v2, v3));
#pragma unroll
                for (int o = 16; o; o >>= 1) mx = fmaxf(mx, __shfl_xor_sync(0xffffffffu, mx, o));
                float e0 = __expf(v0 - mx), e1 = __expf(v1 - mx), e2 = __expf(v2 - mx);
                float e3 = ok3 ? __expf(v3 - mx) : 0.f;
                float ss = e0 + e1 + e2 + e3;
#pragma unroll
                for (int o = 16; o; o >>= 1) ss += __shfl_xor_sync(0xffffffffu, ss, o);
                float r = __fdividef(1.f, ss);
                P[i * 120 + lane]      = __float2bfloat16_rn(e0 * r);
                P[i * 120 + lane + 32] = __float2bfloat16_rn(e1 * r);
                P[i * 120 + lane + 64] = __float2bfloat16_rn(e2 * r);
                if (ok3) P[i * 120 + lane + 96] = __float2bfloat16_rn(e3 * r);
            }
        }
        __syncthreads();

        // PV: AO[:, h*32 .. h*32+31] = P * V_h   (V natural layout, ldmatrix.trans)
        if (wid < 14) {
            int mt = wid >> 1, nt = wid & 1;
            int m0 = mt * 16, n0 = nt * 16;
            float c0[4] = {}, c1[4] = {};
            gemm16<7, 120, 104, true>(P, V + h * 32, m0, n0, lane, c0, c1);
#pragma unroll
            for (int half = 0; half < 2; ++half) {
                float* cc = half ? c1 : c0;
                int col = h * 32 + n0 + half * 8 + 2 * t4;
#pragma unroll
                for (int rh = 0; rh < 2; ++rh)
                    st_bf2(AO + (m0 + g + rh * 8) * 104 + col, cc[rh * 2], cc[rh * 2 + 1]);
            }
        }
        __syncthreads();
    }

    // ---- proj (K=96 over concatenated heads) + bias + residual ----
    for (int mac = wid; mac < 42; mac += 16) {
        int mt = mac / 6, nt = mac % 6;
        int m0 = mt * 16, n0 = nt * 16;
        float c0[4] = {}, c1[4] = {};
        gemm16<6, 104, 104, false>(AO, WP, m0, n0, lane, c0, c1);
#pragma unroll
        for (int half = 0; half < 2; ++half) {
            float* cc = half ? c1 : c0;
            int col = n0 + half * 8 + 2 * t4;
            float pb0 = __ldg(&proj_b[col]), pb1 = __ldg(&proj_b[col + 1]);
#pragma unroll
            for (int rh = 0; rh < 2; ++rh) {
                int trow = m0 + g + rh * 8;
                if (trow < 98) {
                    int off = s_toff[trow] + col;
                    float2 xr = *reinterpret_cast<const float2*>(&x[off]);
                    float2 o2;
                    o2.x = cc[rh * 2]     + pb0 + xr.x;
                    o2.y = cc[rh * 2 + 1] + pb1 + xr.y;
                    *reinterpret_cast<float2*>(&g_xmid[off]) = o2;
                }
            }
        }
    }
}

// ---------------- kernel 2 smem layout ----------------
#define M_X  0            // bf16 [128][104] = 26624
#define M_H  26624        // bf16 [128][104]
#define M_W1 53248        // bf16 [96][104]  = 19968
#define M_W2 73216        // bf16 [96][104]
#define SM2_BYTES 93184

__device__ __forceinline__ float gelu_exact(float v)
{
    return 0.5f * v * (1.f + erff(v * 0.70710678118654752f));
}

__global__ __launch_bounds__(512)
void mlp_kernel(const float* __restrict__ n2w, const float* __restrict__ n2b,
                const float* __restrict__ fc1_b, const float* __restrict__ fc2_b,
                float* __restrict__ out)
{
    extern __shared__ char smc[];
    __nv_bfloat16* X  = (__nv_bfloat16*)(smc + M_X);
    __nv_bfloat16* H  = (__nv_bfloat16*)(smc + M_H);
    __nv_bfloat16* W1 = (__nv_bfloat16*)(smc + M_W1);
    __nv_bfloat16* W2 = (__nv_bfloat16*)(smc + M_W2);

    const int tid = threadIdx.x;
    const int wid = tid >> 5, lane = tid & 31;
    const int g = lane >> 2, t4 = lane & 3;
    const int tbase = blockIdx.x * 128;

    // ---- LN2 -> X bf16 ----
    for (int t = wid; t < 128; t += 16) {
        const float* p = g_xmid + (tbase + t) * 96;
        float v0 = p[lane], v1 = p[lane + 32], v2 = p[lane + 64];
        float s = v0 + v1 + v2;
#pragma unroll
        for (int o = 16; o; o >>= 1) s += __shfl_xor_sync(0xffffffffu, s, o);
        float mean = s * (1.f / 96.f);
        float d0 = v0 - mean, d1 = v1 - mean, d2 = v2 - mean;
        float q2 = d0 * d0 + d1 * d1 + d2 * d2;
#pragma unroll
        for (int o = 16; o; o >>= 1) q2 += __shfl_xor_sync(0xffffffffu, q2, o);
        float rstd = rsqrtf(q2 * (1.f / 96.f) + 1e-5f);
        X[t * 104 + lane] =
            __float2bfloat16_rn(d0 * rstd * __ldg(&n2w[lane]) + __ldg(&n2b[lane]));
        X[t * 104 + lane + 32] =
            __float2bfloat16_rn(d1 * rstd * __ldg(&n2w[lane + 32]) + __ldg(&n2b[lane + 32]));
        X[t * 104 + lane + 64] =
            __float2bfloat16_rn(d2 * rstd * __ldg(&n2w[lane + 64]) + __ldg(&n2b[lane + 64]));
    }

    float c2[3][2][4] = {};   // persistent fc2 accumulators

    for (int ch = 0; ch < 4; ++ch) {
        __syncthreads();
        // stage chunk weights
        for (int idx = tid; idx < 96 * 12; idx += 512) {
            int r = idx / 12, q = idx % 12;
            *reinterpret_cast<uint4*>(W1 + r * 104 + q * 8) =
                *reinterpret_cast<const uint4*>(g_fc1 + (ch * 96 + r) * 96 + q * 8);
            *reinterpret_cast<uint4*>(W2 + r * 104 + q * 8) =
                *reinterpret_cast<const uint4*>(g_fc2 + r * 384 + ch * 96 + q * 8);
        }
        __syncthreads();

        // fc1 chunk + GELU -> H
#pragma unroll
        for (int i = 0; i < 3; ++i) {
            int mac = wid + 16 * i;      // 48 macros: 8m x 6n
            int mt = mac / 6, nt = mac % 6;
            int m0 = mt * 16, n0 = nt * 16;
            float c0[4] = {}, c1[4] = {};
            gemm16<6, 104, 104, false>(X, W1, m0, n0, lane, c0, c1);
#pragma unroll
            for (int half = 0; half < 2; ++half) {
                float* cc = half ? c1 : c0;
                int col = n0 + half * 8 + 2 * t4;
                float b0 = __ldg(&fc1_b[ch * 96 + col]);
                float b1 = __ldg(&fc1_b[ch * 96 + col + 1]);
#pragma unroll
                for (int rh = 0; rh < 2; ++rh)
                    st_bf2(H + (m0 + g + rh * 8) * 104 + col,
                           gelu_exact(cc[rh * 2] + b0), gelu_exact(cc[rh * 2 + 1] + b1));
            }
        }
        __syncthreads();

        // fc2 chunk accumulate
#pragma unroll
        for (int i = 0; i < 3; ++i) {
            int mac = wid + 16 * i;
            int mt = mac / 6, nt = mac % 6;
            gemm16<6, 104, 104, false>(H, W2, mt * 16, nt * 16, lane, c2[i][0], c2[i][1]);
        }
    }

    // ---- epilogue: bias + residual -> out ----
#pragma unroll
    for (int i = 0; i < 3; ++i) {
        int mac = wid + 16 * i;
        int mt = mac / 6, nt = mac % 6;
        int m0 = mt * 16, n0 = nt * 16;
#pragma unroll
        for (int half = 0; half < 2; ++half) {
            int col = n0 + half * 8 + 2 * t4;
            float b0 = __ldg(&fc2_b[col]), b1 = __ldg(&fc2_b[col + 1]);
#pragma unroll
            for (int rh = 0; rh < 2; ++rh) {
                int off = (tbase + m0 + g + rh * 8) * 96 + col;
                float2 xr = *reinterpret_cast<const float2*>(&g_xmid[off]);
                float2 o2;
                o2.x = c2[i][half][rh * 2]     + b0 + xr.x;
                o2.y = c2[i][half][rh * 2 + 1] + b1 + xr.y;
                *reinterpret_cast<float2*>(&out[off]) = o2;
            }
        }
    }
}

// ---------------- launch ----------------
extern "C" void kernel_launch(void* const* d_in, const int* in_sizes, int n_in,
                              void* d_out, int out_size)
{
    const float* x      = (const float*)d_in[0];
    const float* n1w    = (const float*)d_in[1];
    const float* n1b    = (const float*)d_in[2];
    const float* qkv_w  = (const float*)d_in[3];
    const float* qkv_b  = (const float*)d_in[4];
    const float* proj_w = (const float*)d_in[5];
    const float* proj_b = (const float*)d_in[6];
    const float* rpb    = (const float*)d_in[7];
    const float* n2w    = (const float*)d_in[8];
    const float* n2b    = (const float*)d_in[9];
    const float* fc1_w  = (const float*)d_in[10];
    const float* fc1_b  = (const float*)d_in[11];
    const float* fc2_w  = (const float*)d_in[12];
    const float* fc2_b  = (const float*)d_in[13];
    float* out = (float*)d_out;

    cudaFuncSetAttribute(attn_kernel, cudaFuncAttributeMaxDynamicSharedMemorySize, SM1_BYTES);
    cudaFuncSetAttribute(mlp_kernel,  cudaFuncAttributeMaxDynamicSharedMemorySize, SM2_BYTES);

    prep_kernel<<<128, 256>>>(qkv_w, proj_w, fc1_w, fc2_w, rpb);
    attn_kernel<<<NWIN, 512, SM1_BYTES>>>(x, n1w, n1b, qkv_b, proj_b);
    mlp_kernel<<<NTOKENS / 128, 512, SM2_BYTES>>>(n2w, n2b, fc1_b, fc2_b, out);
}

// round 4
// speedup vs baseline: 4.3555x; 1.0028x over previous
#include <cuda_runtime.h>
#include <cuda_bf16.h>
#include <math.h>

#define NWIN    2048
#define NTOKENS 200704
#define XELEMS  (NTOKENS * 96)
#define SCALE   0.17677669529663687f   // 1/sqrt(32)

// ---------------- device scratch ----------------
__device__ float g_xmid[XELEMS];
__device__ __nv_bfloat16 g_bias_bf[3 * 98 * 98];  // [h][i][j]
__device__ __nv_bfloat16 g_wqkv[288 * 96];
__device__ __nv_bfloat16 g_wproj[96 * 96];
__device__ __nv_bfloat16 g_fc1[384 * 96];
__device__ __nv_bfloat16 g_fc2[96 * 384];

// ---------------- prep: bf16 weights + bias table ----------------
__global__ void prep_kernel(const float* __restrict__ qkv_w,
                            const float* __restrict__ proj_w,
                            const float* __restrict__ fc1_w,
                            const float* __restrict__ fc2_w,
                            const float* __restrict__ rpb)
{
    int tid = blockIdx.x * blockDim.x + threadIdx.x;
    int stride = gridDim.x * blockDim.x;
    for (int i = tid; i < 288 * 96; i += stride) g_wqkv[i]  = __float2bfloat16_rn(qkv_w[i]);
    for (int i = tid; i < 96 * 96;  i += stride) g_wproj[i] = __float2bfloat16_rn(proj_w[i]);
    for (int i = tid; i < 384 * 96; i += stride) g_fc1[i]   = __float2bfloat16_rn(fc1_w[i]);
    for (int i = tid; i < 96 * 384; i += stride) g_fc2[i]   = __float2bfloat16_rn(fc2_w[i]);
    for (int idx = tid; idx < 3 * 98 * 98; idx += stride) {
        int h = idx / (98 * 98);
        int r = idx - h * 98 * 98;
        int n = r / 98, m = r - n * 98;
        int nd = n / 49, nh = (n % 49) / 7, nw = n % 7;
        int md = m / 49, mh = (m % 49) / 7, mw = m % 7;
        int rel = (nd - md + 1) * 169 + (nh - mh + 6) * 13 + (nw - mw + 6);
        g_bias_bf[idx] = __float2bfloat16_rn(rpb[rel * 3 + h]);
    }
}

// ---------------- MMA building blocks ----------------
__device__ __forceinline__ unsigned sm_u32(const void* p)
{
    return (unsigned)__cvta_generic_to_shared(p);
}

__device__ __forceinline__ void ldsm4(unsigned addr, unsigned& r0, unsigned& r1,
                                      unsigned& r2, unsigned& r3)
{
    asm volatile("ldmatrix.sync.aligned.m8n8.x4.shared.b16 {%0,%1,%2,%3}, [%4];\n"
                 : "=r"(r0), "=r"(r1), "=r"(r2), "=r"(r3) : "r"(addr));
}

__device__ __forceinline__ void ldsm4t(unsigned addr, unsigned& r0, unsigned& r1,
                                       unsigned& r2, unsigned& r3)
{
    asm volatile("ldmatrix.sync.aligned.m8n8.x4.trans.shared.b16 {%0,%1,%2,%3}, [%4];\n"
                 : "=r"(r0), "=r"(r1), "=r"(r2), "=r"(r3) : "r"(addr));
}

__device__ __forceinline__ void mmabf(float* c, unsigned a0, unsigned a1, unsigned a2,
                                      unsigned a3, unsigned b0, unsigned b1)
{
    asm volatile(
        "mma.sync.aligned.m16n8k16.row.col.f32.bf16.bf16.f32 "
        "{%0,%1,%2,%3}, {%4,%5,%6,%7}, {%8,%9}, {%0,%1,%2,%3};\n"
        : "+f"(c[0]), "+f"(c[1]), "+f"(c[2]), "+f"(c[3])
        : "r"(a0), "r"(a1), "r"(a2), "r"(a3), "r"(b0), "r"(b1));
}

// 16x16 macro-tile. A row-major [m][k]; B either [n][k] row-major (BT=false)
// or natural [k][n] row-major loaded via ldmatrix.trans (BT=true).
template <int KSTEPS, int LDA, int LDB, bool BT>
__device__ __forceinline__ void gemm16(const __nv_bfloat16* __restrict__ A,
                                       const __nv_bfloat16* __restrict__ B,
                                       int m0, int n0, int lane,
                                       float c0[4], float c1[4])
{
    const int l7 = lane & 7;
    const int rowA = m0 + ((lane >> 3) & 1) * 8 + l7;
    const int kA   = ((lane >> 4) & 1) * 8;
    unsigned aA = sm_u32(A + rowA * LDA + kA);
    unsigned aB;
    if (!BT) {
        int rowB = n0 + ((lane >> 4) & 1) * 8 + l7;
        int kB   = ((lane >> 3) & 1) * 8;
        aB = sm_u32(B + rowB * LDB + kB);
    } else {
        int rowB = ((lane >> 3) & 1) * 8 + l7;          // k-row
        int colB = n0 + ((lane >> 4) & 1) * 8;
        aB = sm_u32(B + rowB * LDB + colB);
    }
#pragma unroll
    for (int ks = 0; ks < KSTEPS; ++ks) {
        unsigned a0, a1, a2, a3, b0, b1, b2, b3;
        ldsm4(aA + ks * 32, a0, a1, a2, a3);
        if (!BT) ldsm4(aB + ks * 32, b0, b1, b2, b3);
        else     ldsm4t(aB + ks * 16 * LDB * 2, b0, b1, b2, b3);
        mmabf(c0, a0, a1, a2, a3, b0, b1);
        mmabf(c1, a0, a1, a2, a3, b2, b3);
    }
}

__device__ __forceinline__ void st_bf2(__nv_bfloat16* p, float x, float y)
{
    __nv_bfloat162 v;
    v.x = __float2bfloat16_rn(x);
    v.y = __float2bfloat16_rn(y);
    *reinterpret_cast<__nv_bfloat162*>(p) = v;
}

// ---------------- kernel 1 smem layout (bytes) ----------------
#define A_XN 0           // bf16 [112][104] = 23296   (reused as Wproj [96][104])
#define A_SW 23296       // Wqkv bf16 [288][104] = 59904; later S fp32 [112][116] = 51968
#define A_Q  83200       // bf16 [112][104]
#define A_K  106496      // bf16 [112][104]
#define A_V  129792      // bf16 [112][104]
#define A_P  153088      // bf16 [112][120] = 26880
#define A_AO 179968      // bf16 [112][104]
#define SM1_BYTES 203264

__global__ __launch_bounds__(512)
void attn_kernel(const float* __restrict__ x,
                 const float* __restrict__ n1w, const float* __restrict__ n1b,
                 const float* __restrict__ qkv_b, const float* __restrict__ proj_b)
{
    extern __shared__ char smc[];
    __nv_bfloat16* XN = (__nv_bfloat16*)(smc + A_XN);
    float*         S  = (float*)(smc + A_SW);
    __nv_bfloat16* WK = (__nv_bfloat16*)(smc + A_SW);
    __nv_bfloat16* Q  = (__nv_bfloat16*)(smc + A_Q);
    __nv_bfloat16* K  = (__nv_bfloat16*)(smc + A_K);
    __nv_bfloat16* V  = (__nv_bfloat16*)(smc + A_V);
    __nv_bfloat16* P  = (__nv_bfloat16*)(smc + A_P);
    __nv_bfloat16* AO = (__nv_bfloat16*)(smc + A_AO);
    __nv_bfloat16* WP = (__nv_bfloat16*)(smc + A_XN);
    __shared__ int s_toff[98];

    const int tid = threadIdx.x;
    const int wid = tid >> 5, lane = tid & 31;
    const int g = lane >> 2, t4 = lane & 3;

    // window decode
    const int widx = blockIdx.x;
    const int b = widx >> 8;
    const int rr = widx & 255;
    const int dblk = rr >> 6, hblk = (rr >> 3) & 7, wblk = rr & 7;
    if (tid < 98) {
        int wd = (tid >= 49);
        int rem = tid - wd * 49;
        int wh = rem / 7, ww = rem - wh * 7;
        s_toff[tid] = (((b * 8 + dblk * 2 + wd) * 56 + hblk * 7 + wh) * 56 + wblk * 7 + ww) * 96;
    }
    // zero XN pad rows 98..111 and all of P
    for (int i = tid; i < 14 * 104; i += 512) XN[98 * 104 + i] = __float2bfloat16_rn(0.f);
    for (int i = tid; i < 112 * 120 / 2; i += 512) reinterpret_cast<unsigned*>(P)[i] = 0u;

    // stage Wqkv: 288 rows x 96 bf16 -> stride 104
    for (int idx = tid; idx < 288 * 12; idx += 512) {
        int r = idx / 12, q = idx % 12;
        *reinterpret_cast<uint4*>(WK + r * 104 + q * 8) =
            *reinterpret_cast<const uint4*>(g_wqkv + r * 96 + q * 8);
    }

    // ---- LN1 -> XN bf16 [t][c] ----
    for (int t = wid; t < 98; t += 16) {
        int off = s_toff[t];
        float v0 = x[off + lane];
        float v1 = x[off + lane + 32];
        float v2 = x[off + lane + 64];
        float s = v0 + v1 + v2;
#pragma unroll
        for (int o = 16; o; o >>= 1) s += __shfl_xor_sync(0xffffffffu, s, o);
        float mean = s * (1.f / 96.f);
        float d0 = v0 - mean, d1 = v1 - mean, d2 = v2 - mean;
        float q2 = d0 * d0 + d1 * d1 + d2 * d2;
#pragma unroll
        for (int o = 16; o; o >>= 1) q2 += __shfl_xor_sync(0xffffffffu, q2, o);
        float rstd = rsqrtf(q2 * (1.f / 96.f) + 1e-5f);
        XN[t * 104 + lane] =
            __float2bfloat16_rn(d0 * rstd * __ldg(&n1w[lane]) + __ldg(&n1b[lane]));
        XN[t * 104 + lane + 32] =
            __float2bfloat16_rn(d1 * rstd * __ldg(&n1w[lane + 32]) + __ldg(&n1b[lane + 32]));
        XN[t * 104 + lane + 64] =
            __float2bfloat16_rn(d2 * rstd * __ldg(&n1w[lane + 64]) + __ldg(&n1b[lane + 64]));
    }
    __syncthreads();

    // ---- QKV (all heads): C[112 x 288] ----
    for (int mac = wid; mac < 126; mac += 16) {
        int mt = mac / 18, nt = mac % 18;
        int m0 = mt * 16, n0 = nt * 16;
        float c0[4] = {}, c1[4] = {};
        gemm16<6, 104, 104, false>(XN, WK, m0, n0, lane, c0, c1);
        int part = n0 / 96;                // 0=q 1=k 2=v (tiles never straddle)
#pragma unroll
        for (int half = 0; half < 2; ++half) {
            float* cc = half ? c1 : c0;
            int ocol = n0 + half * 8 + 2 * t4;
            int d = ocol - part * 96;
            float b0 = __ldg(&qkv_b[ocol]), b1 = __ldg(&qkv_b[ocol + 1]);
#pragma unroll
            for (int rh = 0; rh < 2; ++rh) {
                int trow = m0 + g + rh * 8;
                float v0 = cc[rh * 2]     + b0;
                float v1 = cc[rh * 2 + 1] + b1;
                if (trow >= 98) { v0 = 0.f; v1 = 0.f; }
                if (part == 0)      st_bf2(Q + trow * 104 + d, v0 * SCALE, v1 * SCALE);
                else if (part == 1) st_bf2(K + trow * 104 + d, v0, v1);
                else                st_bf2(V + trow * 104 + d, v0, v1);
            }
        }
    }
    __syncthreads();

    // stage Wproj into XN space (XN dead from here on)
    for (int idx = tid; idx < 96 * 12; idx += 512) {
        int r = idx / 12, q = idx % 12;
        *reinterpret_cast<uint4*>(WP + r * 104 + q * 8) =
            *reinterpret_cast<const uint4*>(g_wproj + r * 96 + q * 8);
    }

    // ---- per-head attention ----
    for (int h = 0; h < 3; ++h) {
        // S = Q_h K_h^T : C[112 x 112] fp32
        for (int mac = wid; mac < 49; mac += 16) {
            int mt = mac / 7, nt = mac % 7;
            int m0 = mt * 16, n0 = nt * 16;
            float c0[4] = {}, c1[4] = {};
            gemm16<2, 104, 104, false>(Q + h * 32, K + h * 32, m0, n0, lane, c0, c1);
#pragma unroll
            for (int half = 0; half < 2; ++half) {
                float* cc = half ? c1 : c0;
                int col = n0 + half * 8 + 2 * t4;
#pragma unroll
                for (int rh = 0; rh < 2; ++rh)
                    *reinterpret_cast<float2*>(&S[(m0 + g + rh * 8) * 116 + col]) =
                        make_float2(cc[rh * 2], cc[rh * 2 + 1]);
            }
        }
        __syncthreads();

        // softmax rows + bias -> P bf16
        {
            const __nv_bfloat16* biash = g_bias_bf + h * 98 * 98;
            for (int i = wid; i < 98; i += 16) {
                float* row = S + i * 116;
                const __nv_bfloat16* brow = biash + i * 98;
                float v0 = row[lane]      + __bfloat162float(brow[lane]);
                float v1 = row[lane + 32] + __bfloat162float(brow[lane + 32]);
                float v2 = row[lane + 64] + __bfloat162float(brow[lane + 64]);
                bool ok3 = (lane < 2);
                float v3 = ok3 ? row[lane + 96] + __bfloat162float(brow[lane + 96]) : -1e30f;
                float mx = fmaxf(fmaxf(v0, v1), fmaxf(v2, v3));
#pragma unroll
                for (int o = 16; o; o >>= 1) mx = fmaxf(mx, __shfl_xor_sync(0xffffffffu, mx, o));
                float e0 = __expf(v0 - mx), e1 = __expf(v1 - mx), e2 = __expf(v2 - mx);
                float e3 = ok3 ? __expf(v3 - mx) : 0.f;
                float ss = e0 + e1 + e2 + e3;
#pragma unroll
                for (int o = 16; o; o >>= 1) ss += __shfl_xor_sync(0xffffffffu, ss, o);
                float r = __fdividef(1.f, ss);
                P[i * 120 + lane]      = __float2bfloat16_rn(e0 * r);
                P[i * 120 + lane + 32] = __float2bfloat16_rn(e1 * r);
                P[i * 120 + lane + 64] = __float2bfloat16_rn(e2 * r);
                if (ok3) P[i * 120 + lane + 96] = __float2bfloat16_rn(e3 * r);
            }
        }
        __syncthreads();

        // PV: AO[:, h*32 .. h*32+31] = P * V_h   (V natural layout, ldmatrix.trans)
        if (wid < 14) {
            int mt = wid >> 1, nt = wid & 1;
            int m0 = mt * 16, n0 = nt * 16;
            float c0[4] = {}, c1[4] = {};
            gemm16<7, 120, 104, true>(P, V + h * 32, m0, n0, lane, c0, c1);
#pragma unroll
            for (int half = 0; half < 2; ++half) {
                float* cc = half ? c1 : c0;
                int col = h * 32 + n0 + half * 8 + 2 * t4;
#pragma unroll
                for (int rh = 0; rh < 2; ++rh)
                    st_bf2(AO + (m0 + g + rh * 8) * 104 + col, cc[rh * 2], cc[rh * 2 + 1]);
            }
        }
        __syncthreads();
    }

    // ---- proj (K=96 over concatenated heads) + bias + residual ----
    for (int mac = wid; mac < 42; mac += 16) {
        int mt = mac / 6, nt = mac % 6;
        int m0 = mt * 16, n0 = nt * 16;
        float c0[4] = {}, c1[4] = {};
        gemm16<6, 104, 104, false>(AO, WP, m0, n0, lane, c0, c1);
#pragma unroll
        for (int half = 0; half < 2; ++half) {
            float* cc = half ? c1 : c0;
            int col = n0 + half * 8 + 2 * t4;
            float pb0 = __ldg(&proj_b[col]), pb1 = __ldg(&proj_b[col + 1]);
#pragma unroll
            for (int rh = 0; rh < 2; ++rh) {
                int trow = m0 + g + rh * 8;
                if (trow < 98) {
                    int off = s_toff[trow] + col;
                    float2 xr = *reinterpret_cast<const float2*>(&x[off]);
                    float2 o2;
                    o2.x = cc[rh * 2]     + pb0 + xr.x;
                    o2.y = cc[rh * 2 + 1] + pb1 + xr.y;
                    *reinterpret_cast<float2*>(&g_xmid[off]) = o2;
                }
            }
        }
    }
}

// ---------------- kernel 2 smem layout ----------------
#define M_X  0            // bf16 [128][104] = 26624
#define M_H  26624        // bf16 [128][104]
#define M_W1 53248        // bf16 [96][104]  = 19968
#define M_W2 73216        // bf16 [96][104]
#define SM2_BYTES 93184

__device__ __forceinline__ float gelu_exact(float v)
{
    return 0.5f * v * (1.f + erff(v * 0.70710678118654752f));
}

__global__ __launch_bounds__(512)
void mlp_kernel(const float* __restrict__ n2w, const float* __restrict__ n2b,
                const float* __restrict__ fc1_b, const float* __restrict__ fc2_b,
                float* __restrict__ out)
{
    extern __shared__ char smc[];
    __nv_bfloat16* X  = (__nv_bfloat16*)(smc + M_X);
    __nv_bfloat16* H  = (__nv_bfloat16*)(smc + M_H);
    __nv_bfloat16* W1 = (__nv_bfloat16*)(smc + M_W1);
    __nv_bfloat16* W2 = (__nv_bfloat16*)(smc + M_W2);

    const int tid = threadIdx.x;
    const int wid = tid >> 5, lane = tid & 31;
    const int g = lane >> 2, t4 = lane & 3;
    const int tbase = blockIdx.x * 128;

    // ---- LN2 -> X bf16 ----
    for (int t = wid; t < 128; t += 16) {
        const float* p = g_xmid + (tbase + t) * 96;
        float v0 = p[lane], v1 = p[lane + 32], v2 = p[lane + 64];
        float s = v0 + v1 + v2;
#pragma unroll
        for (int o = 16; o; o >>= 1) s += __shfl_xor_sync(0xffffffffu, s, o);
        float mean = s * (1.f / 96.f);
        float d0 = v0 - mean, d1 = v1 - mean, d2 = v2 - mean;
        float q2 = d0 * d0 + d1 * d1 + d2 * d2;
#pragma unroll
        for (int o = 16; o; o >>= 1) q2 += __shfl_xor_sync(0xffffffffu, q2, o);
        float rstd = rsqrtf(q2 * (1.f / 96.f) + 1e-5f);
        X[t * 104 + lane] =
            __float2bfloat16_rn(d0 * rstd * __ldg(&n2w[lane]) + __ldg(&n2b[lane]));
        X[t * 104 + lane + 32] =
            __float2bfloat16_rn(d1 * rstd * __ldg(&n2w[lane + 32]) + __ldg(&n2b[lane + 32]));
        X[t * 104 + lane + 64] =
            __float2bfloat16_rn(d2 * rstd * __ldg(&n2w[lane + 64]) + __ldg(&n2b[lane + 64]));
    }

    float c2[3][2][4] = {};   // persistent fc2 accumulators

    for (int ch = 0; ch < 4; ++ch) {
        __syncthreads();
        // stage chunk weights
        for (int idx = tid; idx < 96 * 12; idx += 512) {
            int r = idx / 12, q = idx % 12;
            *reinterpret_cast<uint4*>(W1 + r * 104 + q * 8) =
                *reinterpret_cast<const uint4*>(g_fc1 + (ch * 96 + r) * 96 + q * 8);
            *reinterpret_cast<uint4*>(W2 + r * 104 + q * 8) =
                *reinterpret_cast<const uint4*>(g_fc2 + r * 384 + ch * 96 + q * 8);
        }
        __syncthreads();

        // fc1 chunk + GELU -> H
#pragma unroll
        for (int i = 0; i < 3; ++i) {
            int mac = wid + 16 * i;      // 48 macros: 8m x 6n
            int mt = mac / 6, nt = mac % 6;
            int m0 = mt * 16, n0 = nt * 16;
            float c0[4] = {}, c1[4] = {};
            gemm16<6, 104, 104, false>(X, W1, m0, n0, lane, c0, c1);
#pragma unroll
            for (int half = 0; half < 2; ++half) {
                float* cc = half ? c1 : c0;
                int col = n0 + half * 8 + 2 * t4;
                float b0 = __ldg(&fc1_b[ch * 96 + col]);
                float b1 = __ldg(&fc1_b[ch * 96 + col + 1]);
#pragma unroll
                for (int rh = 0; rh < 2; ++rh)
                    st_bf2(H + (m0 + g + rh * 8) * 104 + col,
                           gelu_exact(cc[rh * 2] + b0), gelu_exact(cc[rh * 2 + 1] + b1));
            }
        }
        __syncthreads();

        // fc2 chunk accumulate
#pragma unroll
        for (int i = 0; i < 3; ++i) {
            int mac = wid + 16 * i;
            int mt = mac / 6, nt = mac % 6;
            gemm16<6, 104, 104, false>(H, W2, mt * 16, nt * 16, lane, c2[i][0], c2[i][1]);
        }
    }

    // ---- epilogue: bias + residual -> out ----
#pragma unroll
    for (int i = 0; i < 3; ++i) {
        int mac = wid + 16 * i;
        int mt = mac / 6, nt = mac % 6;
        int m0 = mt * 16, n0 = nt * 16;
#pragma unroll
        for (int half = 0; half < 2; ++half) {
            int col = n0 + half * 8 + 2 * t4;
            float b0 = __ldg(&fc2_b[col]), b1 = __ldg(&fc2_b[col + 1]);
#pragma unroll
            for (int rh = 0; rh < 2; ++rh) {
                int off = (tbase + m0 + g + rh * 8) * 96 + col;
                float2 xr = *reinterpret_cast<const float2*>(&g_xmid[off]);
                float2 o2;
                o2.x = c2[i][half][rh * 2]     + b0 + xr.x;
                o2.y = c2[i][half][rh * 2 + 1] + b1 + xr.y;
                *reinterpret_cast<float2*>(&out[off]) = o2;
            }
        }
    }
}

// ---------------- launch ----------------
extern "C" void kernel_launch(void* const* d_in, const int* in_sizes, int n_in,
                              void* d_out, int out_size)
{
    const float* x      = (const float*)d_in[0];
    const float* n1w    = (const float*)d_in[1];
    const float* n1b    = (const float*)d_in[2];
    const float* qkv_w  = (const float*)d_in[3];
    const float* qkv_b  = (const float*)d_in[4];
    const float* proj_w = (const float*)d_in[5];
    const float* proj_b = (const float*)d_in[6];
    const float* rpb    = (const float*)d_in[7];
    const float* n2w    = (const float*)d_in[8];
    const float* n2b    = (const float*)d_in[9];
    const float* fc1_w  = (const float*)d_in[10];
    const float* fc1_b  = (const float*)d_in[11];
    const float* fc2_w  = (const float*)d_in[12];
    const float* fc2_b  = (const float*)d_in[13];
    float* out = (float*)d_out;

    cudaFuncSetAttribute(attn_kernel, cudaFuncAttributeMaxDynamicSharedMemorySize, SM1_BYTES);
    cudaFuncSetAttribute(mlp_kernel,  cudaFuncAttributeMaxDynamicSharedMemorySize, SM2_BYTES);

    prep_kernel<<<128, 256>>>(qkv_w, proj_w, fc1_w, fc2_w, rpb);
    attn_kernel<<<NWIN, 512, SM1_BYTES>>>(x, n1w, n1b, qkv_b, proj_b);
    mlp_kernel<<<NTOKENS / 128, 512, SM2_BYTES>>>(n2w, n2b, fc1_b, fc2_b, out);
}

// round 5
// speedup vs baseline: 5.7971x; 1.3310x over previous
#include <cuda_runtime.h>
#include <cuda_bf16.h>
#include <math.h>

#define NWIN    2048
#define NTOKENS 200704
#define XELEMS  (NTOKENS * 96)
#define SCALE   0.17677669529663687f   // 1/sqrt(32)

// ---------------- device scratch ----------------
__device__ float g_xmid[XELEMS];
__device__ __nv_bfloat16 g_bias_bf[3 * 98 * 98];  // [h][i][j]
__device__ __nv_bfloat16 g_wqkv[288 * 96];
__device__ __nv_bfloat16 g_wproj[96 * 96];
__device__ __nv_bfloat16 g_fc1[384 * 96];
__device__ __nv_bfloat16 g_fc2[96 * 384];

// ---------------- prep ----------------
__global__ void prep_kernel(const float* __restrict__ qkv_w,
                            const float* __restrict__ proj_w,
                            const float* __restrict__ fc1_w,
                            const float* __restrict__ fc2_w,
                            const float* __restrict__ rpb)
{
    int tid = blockIdx.x * blockDim.x + threadIdx.x;
    int stride = gridDim.x * blockDim.x;
    for (int i = tid; i < 288 * 96; i += stride) g_wqkv[i]  = __float2bfloat16_rn(qkv_w[i]);
    for (int i = tid; i < 96 * 96;  i += stride) g_wproj[i] = __float2bfloat16_rn(proj_w[i]);
    for (int i = tid; i < 384 * 96; i += stride) g_fc1[i]   = __float2bfloat16_rn(fc1_w[i]);
    for (int i = tid; i < 96 * 384; i += stride) g_fc2[i]   = __float2bfloat16_rn(fc2_w[i]);
    for (int idx = tid; idx < 3 * 98 * 98; idx += stride) {
        int h = idx / (98 * 98);
        int r = idx - h * 98 * 98;
        int n = r / 98, m = r - n * 98;
        int nd = n / 49, nh = (n % 49) / 7, nw = n % 7;
        int md = m / 49, mh = (m % 49) / 7, mw = m % 7;
        int rel = (nd - md + 1) * 169 + (nh - mh + 6) * 13 + (nw - mw + 6);
        g_bias_bf[idx] = __float2bfloat16_rn(rpb[rel * 3 + h]);
    }
}

// ---------------- MMA building blocks ----------------
__device__ __forceinline__ unsigned sm_u32(const void* p)
{
    return (unsigned)__cvta_generic_to_shared(p);
}

__device__ __forceinline__ void ldsm4(unsigned addr, unsigned& r0, unsigned& r1,
                                      unsigned& r2, unsigned& r3)
{
    asm volatile("ldmatrix.sync.aligned.m8n8.x4.shared.b16 {%0,%1,%2,%3}, [%4];\n"
                 : "=r"(r0), "=r"(r1), "=r"(r2), "=r"(r3) : "r"(addr));
}

__device__ __forceinline__ void ldsm4t(unsigned addr, unsigned& r0, unsigned& r1,
                                       unsigned& r2, unsigned& r3)
{
    asm volatile("ldmatrix.sync.aligned.m8n8.x4.trans.shared.b16 {%0,%1,%2,%3}, [%4];\n"
                 : "=r"(r0), "=r"(r1), "=r"(r2), "=r"(r3) : "r"(addr));
}

__device__ __forceinline__ void mmabf(float* c, unsigned a0, unsigned a1, unsigned a2,
                                      unsigned a3, unsigned b0, unsigned b1)
{
    asm volatile(
        "mma.sync.aligned.m16n8k16.row.col.f32.bf16.bf16.f32 "
        "{%0,%1,%2,%3}, {%4,%5,%6,%7}, {%8,%9}, {%0,%1,%2,%3};\n"
        : "+f"(c[0]), "+f"(c[1]), "+f"(c[2]), "+f"(c[3])
        : "r"(a0), "r"(a1), "r"(a2), "r"(a3), "r"(b0), "r"(b1));
}

// 16x16 macro-tile, A row-major [m][k], B row-major [n][k]
template <int KSTEPS, int LDA, int LDB>
__device__ __forceinline__ void gemm16(const __nv_bfloat16* __restrict__ A,
                                       const __nv_bfloat16* __restrict__ B,
                                       int m0, int n0, int lane,
                                       float c0[4], float c1[4])
{
    const int l7 = lane & 7;
    unsigned aA = sm_u32(A + (m0 + ((lane >> 3) & 1) * 8 + l7) * LDA + ((lane >> 4) & 1) * 8);
    unsigned aB = sm_u32(B + (n0 + ((lane >> 4) & 1) * 8 + l7) * LDB + ((lane >> 3) & 1) * 8);
#pragma unroll
    for (int ks = 0; ks < KSTEPS; ++ks) {
        unsigned a0, a1, a2, a3, b0, b1, b2, b3;
        ldsm4(aA + ks * 32, a0, a1, a2, a3);
        ldsm4(aB + ks * 32, b0, b1, b2, b3);
        mmabf(c0, a0, a1, a2, a3, b0, b1);
        mmabf(c1, a0, a1, a2, a3, b2, b3);
    }
}

__device__ __forceinline__ void st_bf2(__nv_bfloat16* p, float x, float y)
{
    __nv_bfloat162 v = __floats2bfloat162_rn(x, y);
    *reinterpret_cast<__nv_bfloat162*>(p) = v;
}

__device__ __forceinline__ unsigned pack_bf2(float x, float y)
{
    __nv_bfloat162 v = __floats2bfloat162_rn(x, y);
    return *reinterpret_cast<unsigned*>(&v);
}

// ---------------- kernel 1 smem layout (bytes) ----------------
// XN/AO bf16[112][104] @0, Q @23296, K @46592, V @69888, W bf16[96][104] @93184
#define A_XN 0
#define A_Q  23296
#define A_K  46592
#define A_V  69888
#define A_W  93184
#define SM1_BYTES 113152

__global__ __launch_bounds__(256, 2)
void attn_kernel(const float* __restrict__ x,
                 const float* __restrict__ n1w, const float* __restrict__ n1b,
                 const float* __restrict__ qkv_b, const float* __restrict__ proj_b)
{
    extern __shared__ char smc[];
    __nv_bfloat16* XN = (__nv_bfloat16*)(smc + A_XN);
    __nv_bfloat16* AO = (__nv_bfloat16*)(smc + A_XN);
    __nv_bfloat16* Q  = (__nv_bfloat16*)(smc + A_Q);
    __nv_bfloat16* K  = (__nv_bfloat16*)(smc + A_K);
    __nv_bfloat16* V  = (__nv_bfloat16*)(smc + A_V);
    __nv_bfloat16* W  = (__nv_bfloat16*)(smc + A_W);
    __shared__ int s_toff[98];

    const int tid = threadIdx.x;
    const int wid = tid >> 5, lane = tid & 31;
    const int g = lane >> 2, t4 = lane & 3;

    // window decode
    const int widx = blockIdx.x;
    const int b = widx >> 8;
    const int rr = widx & 255;
    const int dblk = rr >> 6, hblk = (rr >> 3) & 7, wblk = rr & 7;
    if (tid < 98) {
        int wd = (tid >= 49);
        int rem = tid - wd * 49;
        int wh = rem / 7, ww = rem - wh * 7;
        s_toff[tid] = (((b * 8 + dblk * 2 + wd) * 56 + hblk * 7 + wh) * 56 + wblk * 7 + ww) * 96;
    }
    // zero XN pad rows 98..111
    for (int i = tid; i < 14 * 52; i += 256)
        reinterpret_cast<unsigned*>(XN + 98 * 104)[i] = 0u;
    __syncthreads();

    // ---- LN1 -> XN bf16 [t][c] + stage Wq ----
    for (int t = wid; t < 98; t += 8) {
        int off = s_toff[t];
        float v0 = x[off + lane];
        float v1 = x[off + lane + 32];
        float v2 = x[off + lane + 64];
        float s = v0 + v1 + v2;
#pragma unroll
        for (int o = 16; o; o >>= 1) s += __shfl_xor_sync(0xffffffffu, s, o);
        float mean = s * (1.f / 96.f);
        float d0 = v0 - mean, d1 = v1 - mean, d2 = v2 - mean;
        float q2 = d0 * d0 + d1 * d1 + d2 * d2;
#pragma unroll
        for (int o = 16; o; o >>= 1) q2 += __shfl_xor_sync(0xffffffffu, q2, o);
        float rstd = rsqrtf(q2 * (1.f / 96.f) + 1e-5f);
        XN[t * 104 + lane] =
            __float2bfloat16_rn(d0 * rstd * __ldg(&n1w[lane]) + __ldg(&n1b[lane]));
        XN[t * 104 + lane + 32] =
            __float2bfloat16_rn(d1 * rstd * __ldg(&n1w[lane + 32]) + __ldg(&n1b[lane + 32]));
        XN[t * 104 + lane + 64] =
            __float2bfloat16_rn(d2 * rstd * __ldg(&n1w[lane + 64]) + __ldg(&n1b[lane + 64]));
    }

    // ---- Q, K, V gemms with per-part staged weights ----
    for (int part = 0; part < 3; ++part) {
        for (int idx = tid; idx < 96 * 12; idx += 256) {
            int r = idx / 12, q = idx % 12;
            *reinterpret_cast<uint4*>(W + r * 104 + q * 8) =
                *reinterpret_cast<const uint4*>(g_wqkv + part * 9216 + r * 96 + q * 8);
        }
        __syncthreads();
        __nv_bfloat16* DST = (part == 0) ? Q : (part == 1) ? K : V;
        for (int mac = wid; mac < 42; mac += 8) {
            int mt = mac / 6, nt = mac % 6;
            int m0 = mt * 16, n0 = nt * 16;
            float c0[4] = {}, c1[4] = {};
            gemm16<6, 104, 104>(XN, W, m0, n0, lane, c0, c1);
#pragma unroll
            for (int half = 0; half < 2; ++half) {
                float* cc = half ? c1 : c0;
                int d = n0 + half * 8 + 2 * t4;
                float b0 = __ldg(&qkv_b[part * 96 + d]);
                float b1 = __ldg(&qkv_b[part * 96 + d + 1]);
#pragma unroll
                for (int rh = 0; rh < 2; ++rh) {
                    int trow = m0 + g + rh * 8;
                    float v0 = cc[rh * 2]     + b0;
                    float v1 = cc[rh * 2 + 1] + b1;
                    if (trow >= 98) { v0 = 0.f; v1 = 0.f; }
                    if (part == 0) { v0 *= SCALE; v1 *= SCALE; }
                    st_bf2(DST + trow * 104 + d, v0, v1);
                }
            }
        }
        __syncthreads();
    }

    // ---- stage Wproj (W buffer now free) + attention in registers ----
    for (int idx = tid; idx < 96 * 12; idx += 256) {
        int r = idx / 12, q = idx % 12;
        *reinterpret_cast<uint4*>(W + r * 104 + q * 8) =
            *reinterpret_cast<const uint4*>(g_wproj + r * 96 + q * 8);
    }

    const int l7 = lane & 7;
    for (int unit = wid; unit < 21; unit += 8) {
        int h = unit / 7, m0 = (unit % 7) * 16;
        const __nv_bfloat16* Qh = Q + h * 32;
        const __nv_bfloat16* Kh = K + h * 32;

        // Q A-fragments (rows m0.., k=0..31)
        unsigned qa[2][4];
        {
            unsigned aA = sm_u32(Qh + (m0 + ((lane >> 3) & 1) * 8 + l7) * 104 +
                                 ((lane >> 4) & 1) * 8);
            ldsm4(aA,      qa[0][0], qa[0][1], qa[0][2], qa[0][3]);
            ldsm4(aA + 32, qa[1][0], qa[1][1], qa[1][2], qa[1][3]);
        }

        // S strip [16 x 112] in registers
        float s[7][2][4];
#pragma unroll
        for (int j = 0; j < 7; ++j) {
#pragma unroll
            for (int hf = 0; hf < 2; ++hf)
#pragma unroll
                for (int e = 0; e < 4; ++e) s[j][hf][e] = 0.f;
            unsigned aB = sm_u32(Kh + (j * 16 + ((lane >> 4) & 1) * 8 + l7) * 104 +
                                 ((lane >> 3) & 1) * 8);
#pragma unroll
            for (int ks = 0; ks < 2; ++ks) {
                unsigned b0, b1, b2, b3;
                ldsm4(aB + ks * 32, b0, b1, b2, b3);
                mmabf(s[j][0], qa[ks][0], qa[ks][1], qa[ks][2], qa[ks][3], b0, b1);
                mmabf(s[j][1], qa[ks][0], qa[ks][1], qa[ks][2], qa[ks][3], b2, b3);
            }
        }

        // bias + mask + softmax (rows g and g+8; reduce over t4 group)
        int i0 = m0 + g;     if (i0 > 97) i0 = 97;
        int i1 = m0 + g + 8; if (i1 > 97) i1 = 97;
        const __nv_bfloat16* bi0 = g_bias_bf + h * 9604 + i0 * 98;
        const __nv_bfloat16* bi1 = g_bias_bf + h * 9604 + i1 * 98;
        float mx0 = -1e30f, mx1 = -1e30f;
#pragma unroll
        for (int j = 0; j < 7; ++j) {
#pragma unroll
            for (int hf = 0; hf < 2; ++hf) {
                int col = 16 * j + 8 * hf + 2 * t4;
                if (col < 98) {
                    __nv_bfloat162 b0 = *reinterpret_cast<const __nv_bfloat162*>(bi0 + col);
                    __nv_bfloat162 b1 = *reinterpret_cast<const __nv_bfloat162*>(bi1 + col);
                    s[j][hf][0] += __bfloat162float(b0.x);
                    s[j][hf][1] += __bfloat162float(b0.y);
                    s[j][hf][2] += __bfloat162float(b1.x);
                    s[j][hf][3] += __bfloat162float(b1.y);
                    mx0 = fmaxf(mx0, fmaxf(s[j][hf][0], s[j][hf][1]));
                    mx1 = fmaxf(mx1, fmaxf(s[j][hf][2], s[j][hf][3]));
                } else {
                    s[j][hf][0] = -1e30f; s[j][hf][1] = -1e30f;
                    s[j][hf][2] = -1e30f; s[j][hf][3] = -1e30f;
                }
            }
        }
        mx0 = fmaxf(mx0, __shfl_xor_sync(0xffffffffu, mx0, 1));
        mx0 = fmaxf(mx0, __shfl_xor_sync(0xffffffffu, mx0, 2));
        mx1 = fmaxf(mx1, __shfl_xor_sync(0xffffffffu, mx1, 1));
        mx1 = fmaxf(mx1, __shfl_xor_sync(0xffffffffu, mx1, 2));
        float sum0 = 0.f, sum1 = 0.f;
#pragma unroll
        for (int j = 0; j < 7; ++j)
#pragma unroll
            for (int hf = 0; hf < 2; ++hf) {
                s[j][hf][0] = __expf(s[j][hf][0] - mx0);
                s[j][hf][1] = __expf(s[j][hf][1] - mx0);
                s[j][hf][2] = __expf(s[j][hf][2] - mx1);
                s[j][hf][3] = __expf(s[j][hf][3] - mx1);
                sum0 += s[j][hf][0] + s[j][hf][1];
                sum1 += s[j][hf][2] + s[j][hf][3];
            }
        sum0 += __shfl_xor_sync(0xffffffffu, sum0, 1);
        sum0 += __shfl_xor_sync(0xffffffffu, sum0, 2);
        sum1 += __shfl_xor_sync(0xffffffffu, sum1, 1);
        sum1 += __shfl_xor_sync(0xffffffffu, sum1, 2);
        float r0 = __fdividef(1.f, sum0), r1 = __fdividef(1.f, sum1);

        // pack P straight into A-fragments
        unsigned pa[7][4];
#pragma unroll
        for (int j = 0; j < 7; ++j) {
            pa[j][0] = pack_bf2(s[j][0][0] * r0, s[j][0][1] * r0);
            pa[j][1] = pack_bf2(s[j][0][2] * r1, s[j][0][3] * r1);
            pa[j][2] = pack_bf2(s[j][1][0] * r0, s[j][1][1] * r0);
            pa[j][3] = pack_bf2(s[j][1][2] * r1, s[j][1][3] * r1);
        }

        // PV: [16 x 32] via ldmatrix.trans on V natural layout
        float o[2][2][4] = {};
#pragma unroll
        for (int j = 0; j < 7; ++j) {
            unsigned vb = sm_u32(V + (j * 16 + ((lane >> 3) & 1) * 8 + l7) * 104 +
                                 h * 32 + ((lane >> 4) & 1) * 8);
            unsigned b0, b1, b2, b3;
            ldsm4t(vb, b0, b1, b2, b3);
            mmabf(o[0][0], pa[j][0], pa[j][1], pa[j][2], pa[j][3], b0, b1);
            mmabf(o[0][1], pa[j][0], pa[j][1], pa[j][2], pa[j][3], b2, b3);
            ldsm4t(vb + 32, b0, b1, b2, b3);
            mmabf(o[1][0], pa[j][0], pa[j][1], pa[j][2], pa[j][3], b0, b1);
            mmabf(o[1][1], pa[j][0], pa[j][1], pa[j][2], pa[j][3], b2, b3);
        }

        // store AO strip
#pragma unroll
        for (int nc = 0; nc < 2; ++nc)
#pragma unroll
            for (int hf = 0; hf < 2; ++hf) {
                int col = h * 32 + nc * 16 + hf * 8 + 2 * t4;
#pragma unroll
                for (int rh = 0; rh < 2; ++rh)
                    st_bf2(AO + (m0 + g + rh * 8) * 104 + col,
                           o[nc][hf][rh * 2], o[nc][hf][rh * 2 + 1]);
            }
    }
    __syncthreads();

    // ---- proj + bias + residual ----
    for (int mac = wid; mac < 42; mac += 8) {
        int mt = mac / 6, nt = mac % 6;
        int m0 = mt * 16, n0 = nt * 16;
        float c0[4] = {}, c1[4] = {};
        gemm16<6, 104, 104>(AO, W, m0, n0, lane, c0, c1);
#pragma unroll
        for (int half = 0; half < 2; ++half) {
            float* cc = half ? c1 : c0;
            int col = n0 + half * 8 + 2 * t4;
            float pb0 = __ldg(&proj_b[col]), pb1 = __ldg(&proj_b[col + 1]);
#pragma unroll
            for (int rh = 0; rh < 2; ++rh) {
                int trow = m0 + g + rh * 8;
                if (trow < 98) {
                    int off = s_toff[trow] + col;
                    float2 xr = *reinterpret_cast<const float2*>(&x[off]);
                    float2 o2;
                    o2.x = cc[rh * 2]     + pb0 + xr.x;
                    o2.y = cc[rh * 2 + 1] + pb1 + xr.y;
                    *reinterpret_cast<float2*>(&g_xmid[off]) = o2;
                }
            }
        }
    }
}

// ---------------- kernel 2 smem layout ----------------
#define M_X  0            // bf16 [128][104] = 26624
#define M_H  26624        // bf16 [128][104]
#define M_W1 53248        // bf16 [96][104]  = 19968
#define M_W2 73216        // bf16 [96][104]
#define SM2_BYTES 93184

__device__ __forceinline__ float gelu_exact(float v)
{
    return 0.5f * v * (1.f + erff(v * 0.70710678118654752f));
}

__global__ __launch_bounds__(512)
void mlp_kernel(const float* __restrict__ n2w, const float* __restrict__ n2b,
                const float* __restrict__ fc1_b, const float* __restrict__ fc2_b,
                float* __restrict__ out)
{
    extern __shared__ char smc[];
    __nv_bfloat16* X  = (__nv_bfloat16*)(smc + M_X);
    __nv_bfloat16* H  = (__nv_bfloat16*)(smc + M_H);
    __nv_bfloat16* W1 = (__nv_bfloat16*)(smc + M_W1);
    __nv_bfloat16* W2 = (__nv_bfloat16*)(smc + M_W2);

    const int tid = threadIdx.x;
    const int wid = tid >> 5, lane = tid & 31;
    const int g = lane >> 2, t4 = lane & 3;
    const int tbase = blockIdx.x * 128;

    // ---- LN2 -> X bf16 ----
    for (int t = wid; t < 128; t += 16) {
        const float* p = g_xmid + (tbase + t) * 96;
        float v0 = p[lane], v1 = p[lane + 32], v2 = p[lane + 64];
        float s = v0 + v1 + v2;
#pragma unroll
        for (int o = 16; o; o >>= 1) s += __shfl_xor_sync(0xffffffffu, s, o);
        float mean = s * (1.f / 96.f);
        float d0 = v0 - mean, d1 = v1 - mean, d2 = v2 - mean;
        float q2 = d0 * d0 + d1 * d1 + d2 * d2;
#pragma unroll
        for (int o = 16; o; o >>= 1) q2 += __shfl_xor_sync(0xffffffffu, q2, o);
        float rstd = rsqrtf(q2 * (1.f / 96.f) + 1e-5f);
        X[t * 104 + lane] =
            __float2bfloat16_rn(d0 * rstd * __ldg(&n2w[lane]) + __ldg(&n2b[lane]));
        X[t * 104 + lane + 32] =
            __float2bfloat16_rn(d1 * rstd * __ldg(&n2w[lane + 32]) + __ldg(&n2b[lane + 32]));
        X[t * 104 + lane + 64] =
            __float2bfloat16_rn(d2 * rstd * __ldg(&n2w[lane + 64]) + __ldg(&n2b[lane + 64]));
    }

    float c2[3][2][4] = {};   // persistent fc2 accumulators

    for (int ch = 0; ch < 4; ++ch) {
        __syncthreads();
        for (int idx = tid; idx < 96 * 12; idx += 512) {
            int r = idx / 12, q = idx % 12;
            *reinterpret_cast<uint4*>(W1 + r * 104 + q * 8) =
                *reinterpret_cast<const uint4*>(g_fc1 + (ch * 96 + r) * 96 + q * 8);
            *reinterpret_cast<uint4*>(W2 + r * 104 + q * 8) =
                *reinterpret_cast<const uint4*>(g_fc2 + r * 384 + ch * 96 + q * 8);
        }
        __syncthreads();

        // fc1 chunk + GELU -> H
#pragma unroll
        for (int i = 0; i < 3; ++i) {
            int mac = wid + 16 * i;      // 48 macros: 8m x 6n
            int mt = mac / 6, nt = mac % 6;
            int m0 = mt * 16, n0 = nt * 16;
            float c0[4] = {}, c1[4] = {};
            gemm16<6, 104, 104>(X, W1, m0, n0, lane, c0, c1);
#pragma unroll
            for (int half = 0; half < 2; ++half) {
                float* cc = half ? c1 : c0;
                int col = n0 + half * 8 + 2 * t4;
                float b0 = __ldg(&fc1_b[ch * 96 + col]);
                float b1 = __ldg(&fc1_b[ch * 96 + col + 1]);
#pragma unroll
                for (int rh = 0; rh < 2; ++rh)
                    st_bf2(H + (m0 + g + rh * 8) * 104 + col,
                           gelu_exact(cc[rh * 2] + b0), gelu_exact(cc[rh * 2 + 1] + b1));
            }
        }
        __syncthreads();

        // fc2 chunk accumulate
#pragma unroll
        for (int i = 0; i < 3; ++i) {
            int mac = wid + 16 * i;
            int mt = mac / 6, nt = mac % 6;
            gemm16<6, 104, 104>(H, W2, mt * 16, nt * 16, lane, c2[i][0], c2[i][1]);
        }
    }

    // ---- epilogue: bias + residual -> out ----
#pragma unroll
    for (int i = 0; i < 3; ++i) {
        int mac = wid + 16 * i;
        int mt = mac / 6, nt = mac % 6;
        int m0 = mt * 16, n0 = nt * 16;
#pragma unroll
        for (int half = 0; half < 2; ++half) {
            int col = n0 + half * 8 + 2 * t4;
            float b0 = __ldg(&fc2_b[col]), b1 = __ldg(&fc2_b[col + 1]);
#pragma unroll
            for (int rh = 0; rh < 2; ++rh) {
                int off = (tbase + m0 + g + rh * 8) * 96 + col;
                float2 xr = *reinterpret_cast<const float2*>(&g_xmid[off]);
                float2 o2;
                o2.x = c2[i][half][rh * 2]     + b0 + xr.x;
                o2.y = c2[i][half][rh * 2 + 1] + b1 + xr.y;
                *reinterpret_cast<float2*>(&out[off]) = o2;
            }
        }
    }
}

// ---------------- launch ----------------
extern "C" void kernel_launch(void* const* d_in, const int* in_sizes, int n_in,
                              void* d_out, int out_size)
{
    const float* x      = (const float*)d_in[0];
    const float* n1w    = (const float*)d_in[1];
    const float* n1b    = (const float*)d_in[2];
    const float* qkv_w  = (const float*)d_in[3];
    const float* qkv_b  = (const float*)d_in[4];
    const float* proj_w = (const float*)d_in[5];
    const float* proj_b = (const float*)d_in[6];
    const float* rpb    = (const float*)d_in[7];
    const float* n2w    = (const float*)d_in[8];
    const float* n2b    = (const float*)d_in[9];
    const float* fc1_w  = (const float*)d_in[10];
    const float* fc1_b  = (const float*)d_in[11];
    const float* fc2_w  = (const float*)d_in[12];
    const float* fc2_b  = (const float*)d_in[13];
    float* out = (float*)d_out;

    cudaFuncSetAttribute(attn_kernel, cudaFuncAttributeMaxDynamicSharedMemorySize, SM1_BYTES);
    cudaFuncSetAttribute(mlp_kernel,  cudaFuncAttributeMaxDynamicSharedMemorySize, SM2_BYTES);

    prep_kernel<<<128, 256>>>(qkv_w, proj_w, fc1_w, fc2_w, rpb);
    attn_kernel<<<NWIN, 256, SM1_BYTES>>>(x, n1w, n1b, qkv_b, proj_b);
    mlp_kernel<<<NTOKENS / 128, 512, SM2_BYTES>>>(n2w, n2b, fc1_b, fc2_b, out);
}

// round 6
// speedup vs baseline: 7.1959x; 1.2413x over previous
#include <cuda_runtime.h>
#include <cuda_bf16.h>
#include <math.h>

#define NWIN    2048
#define NTOKENS 200704
#define XELEMS  (NTOKENS * 96)
#define SCALE   0.17677669529663687f   // 1/sqrt(32)

// ---------------- device scratch ----------------
__device__ float g_xmid[XELEMS];
__device__ __nv_bfloat16 g_bias_bf[3 * 98 * 98];  // [h][i][j]
__device__ __nv_bfloat16 g_wqkv[288 * 96];
__device__ __nv_bfloat16 g_wproj[96 * 96];
__device__ __nv_bfloat16 g_fc1[384 * 96];
__device__ __nv_bfloat16 g_fc2[96 * 384];

// ---------------- prep ----------------
__global__ void prep_kernel(const float* __restrict__ qkv_w,
                            const float* __restrict__ proj_w,
                            const float* __restrict__ fc1_w,
                            const float* __restrict__ fc2_w,
                            const float* __restrict__ rpb)
{
    int tid = blockIdx.x * blockDim.x + threadIdx.x;
    int stride = gridDim.x * blockDim.x;
    for (int i = tid; i < 288 * 96; i += stride) g_wqkv[i]  = __float2bfloat16_rn(qkv_w[i]);
    for (int i = tid; i < 96 * 96;  i += stride) g_wproj[i] = __float2bfloat16_rn(proj_w[i]);
    for (int i = tid; i < 384 * 96; i += stride) g_fc1[i]   = __float2bfloat16_rn(fc1_w[i]);
    for (int i = tid; i < 96 * 384; i += stride) g_fc2[i]   = __float2bfloat16_rn(fc2_w[i]);
    for (int idx = tid; idx < 3 * 98 * 98; idx += stride) {
        int h = idx / (98 * 98);
        int r = idx - h * 98 * 98;
        int n = r / 98, m = r - n * 98;
        int nd = n / 49, nh = (n % 49) / 7, nw = n % 7;
        int md = m / 49, mh = (m % 49) / 7, mw = m % 7;
        int rel = (nd - md + 1) * 169 + (nh - mh + 6) * 13 + (nw - mw + 6);
        g_bias_bf[idx] = __float2bfloat16_rn(rpb[rel * 3 + h]);
    }
}

// ---------------- MMA building blocks ----------------
__device__ __forceinline__ unsigned sm_u32(const void* p)
{
    return (unsigned)__cvta_generic_to_shared(p);
}

__device__ __forceinline__ void cpa16(void* dst, const void* src)
{
    asm volatile("cp.async.cg.shared.global [%0], [%1], 16;\n"
                 :: "r"(sm_u32(dst)), "l"(src));
}

__device__ __forceinline__ void cpa_wait()
{
    asm volatile("cp.async.commit_group;\ncp.async.wait_group 0;\n" ::: "memory");
}

__device__ __forceinline__ void ldsm4(unsigned addr, unsigned& r0, unsigned& r1,
                                      unsigned& r2, unsigned& r3)
{
    asm volatile("ldmatrix.sync.aligned.m8n8.x4.shared.b16 {%0,%1,%2,%3}, [%4];\n"
                 : "=r"(r0), "=r"(r1), "=r"(r2), "=r"(r3) : "r"(addr));
}

__device__ __forceinline__ void ldsm4t(unsigned addr, unsigned& r0, unsigned& r1,
                                       unsigned& r2, unsigned& r3)
{
    asm volatile("ldmatrix.sync.aligned.m8n8.x4.trans.shared.b16 {%0,%1,%2,%3}, [%4];\n"
                 : "=r"(r0), "=r"(r1), "=r"(r2), "=r"(r3) : "r"(addr));
}

__device__ __forceinline__ void mmabf(float* c, unsigned a0, unsigned a1, unsigned a2,
                                      unsigned a3, unsigned b0, unsigned b1)
{
    asm volatile(
        "mma.sync.aligned.m16n8k16.row.col.f32.bf16.bf16.f32 "
        "{%0,%1,%2,%3}, {%4,%5,%6,%7}, {%8,%9}, {%0,%1,%2,%3};\n"
        : "+f"(c[0]), "+f"(c[1]), "+f"(c[2]), "+f"(c[3])
        : "r"(a0), "r"(a1), "r"(a2), "r"(a3), "r"(b0), "r"(b1));
}

// 16x32 macro-tile: 3 ldsm per 4 mma
template <int KSTEPS, int LDA, int LDB>
__device__ __forceinline__ void gemm16x32(const __nv_bfloat16* __restrict__ A,
                                          const __nv_bfloat16* __restrict__ B,
                                          int m0, int n0, int lane, float c[4][4])
{
    const int l7 = lane & 7, s8 = (lane >> 3) & 1, s16 = (lane >> 4) & 1;
    unsigned aA  = sm_u32(A + (m0 + s8 * 8 + l7) * LDA + s16 * 8);
    unsigned aB0 = sm_u32(B + (n0 + s16 * 8 + l7) * LDB + s8 * 8);
    unsigned aB1 = aB0 + 16 * LDB * 2;
#pragma unroll
    for (int ks = 0; ks < KSTEPS; ++ks) {
        unsigned a0, a1, a2, a3, b0, b1, b2, b3;
        ldsm4(aA + ks * 32, a0, a1, a2, a3);
        ldsm4(aB0 + ks * 32, b0, b1, b2, b3);
        mmabf(c[0], a0, a1, a2, a3, b0, b1);
        mmabf(c[1], a0, a1, a2, a3, b2, b3);
        ldsm4(aB1 + ks * 32, b0, b1, b2, b3);
        mmabf(c[2], a0, a1, a2, a3, b0, b1);
        mmabf(c[3], a0, a1, a2, a3, b2, b3);
    }
}

// 32x32 macro-tile: 4 ldsm per 8 mma
template <int KSTEPS, int LDA, int LDB>
__device__ __forceinline__ void gemm32x32(const __nv_bfloat16* __restrict__ A,
                                          const __nv_bfloat16* __restrict__ B,
                                          int m0, int n0, int lane, float c[2][4][4])
{
    const int l7 = lane & 7, s8 = (lane >> 3) & 1, s16 = (lane >> 4) & 1;
    unsigned aA0 = sm_u32(A + (m0 + s8 * 8 + l7) * LDA + s16 * 8);
    unsigned aA1 = aA0 + 16 * LDA * 2;
    unsigned aB0 = sm_u32(B + (n0 + s16 * 8 + l7) * LDB + s8 * 8);
    unsigned aB1 = aB0 + 16 * LDB * 2;
#pragma unroll
    for (int ks = 0; ks < KSTEPS; ++ks) {
        unsigned a00, a01, a02, a03, a10, a11, a12, a13, b0, b1, b2, b3;
        ldsm4(aA0 + ks * 32, a00, a01, a02, a03);
        ldsm4(aA1 + ks * 32, a10, a11, a12, a13);
        ldsm4(aB0 + ks * 32, b0, b1, b2, b3);
        mmabf(c[0][0], a00, a01, a02, a03, b0, b1);
        mmabf(c[0][1], a00, a01, a02, a03, b2, b3);
        mmabf(c[1][0], a10, a11, a12, a13, b0, b1);
        mmabf(c[1][1], a10, a11, a12, a13, b2, b3);
        ldsm4(aB1 + ks * 32, b0, b1, b2, b3);
        mmabf(c[0][2], a00, a01, a02, a03, b0, b1);
        mmabf(c[0][3], a00, a01, a02, a03, b2, b3);
        mmabf(c[1][2], a10, a11, a12, a13, b0, b1);
        mmabf(c[1][3], a10, a11, a12, a13, b2, b3);
    }
}

__device__ __forceinline__ void st_bf2(__nv_bfloat16* p, float x, float y)
{
    __nv_bfloat162 v = __floats2bfloat162_rn(x, y);
    *reinterpret_cast<__nv_bfloat162*>(p) = v;
}

__device__ __forceinline__ unsigned pack_bf2(float x, float y)
{
    __nv_bfloat162 v = __floats2bfloat162_rn(x, y);
    return *reinterpret_cast<unsigned*>(&v);
}

// ---------------- kernel 1 smem layout (bytes) ----------------
#define A_XN 0
#define A_Q  23296
#define A_K  46592
#define A_V  69888
#define A_W  93184
#define SM1_BYTES 113152

__global__ __launch_bounds__(256, 2)
void attn_kernel(const float* __restrict__ x,
                 const float* __restrict__ n1w, const float* __restrict__ n1b,
                 const float* __restrict__ qkv_b, const float* __restrict__ proj_b)
{
    extern __shared__ char smc[];
    __nv_bfloat16* XN = (__nv_bfloat16*)(smc + A_XN);
    __nv_bfloat16* AO = (__nv_bfloat16*)(smc + A_XN);
    __nv_bfloat16* Q  = (__nv_bfloat16*)(smc + A_Q);
    __nv_bfloat16* K  = (__nv_bfloat16*)(smc + A_K);
    __nv_bfloat16* V  = (__nv_bfloat16*)(smc + A_V);
    __nv_bfloat16* W  = (__nv_bfloat16*)(smc + A_W);
    __shared__ int s_toff[98];

    const int tid = threadIdx.x;
    const int wid = tid >> 5, lane = tid & 31;
    const int g = lane >> 2, t4 = lane & 3;

    const int widx = blockIdx.x;
    const int b = widx >> 8;
    const int rr = widx & 255;
    const int dblk = rr >> 6, hblk = (rr >> 3) & 7, wblk = rr & 7;
    if (tid < 98) {
        int wd = (tid >= 49);
        int rem = tid - wd * 49;
        int wh = rem / 7, ww = rem - wh * 7;
        s_toff[tid] = (((b * 8 + dblk * 2 + wd) * 56 + hblk * 7 + wh) * 56 + wblk * 7 + ww) * 96;
    }
    for (int i = tid; i < 14 * 52; i += 256)
        reinterpret_cast<unsigned*>(XN + 98 * 104)[i] = 0u;
    __syncthreads();

    // ---- LN1 -> XN bf16 [t][c] ----
    for (int t = wid; t < 98; t += 8) {
        int off = s_toff[t];
        float v0 = x[off + lane];
        float v1 = x[off + lane + 32];
        float v2 = x[off + lane + 64];
        float s = v0 + v1 + v2;
#pragma unroll
        for (int o = 16; o; o >>= 1) s += __shfl_xor_sync(0xffffffffu, s, o);
        float mean = s * (1.f / 96.f);
        float d0 = v0 - mean, d1 = v1 - mean, d2 = v2 - mean;
        float q2 = d0 * d0 + d1 * d1 + d2 * d2;
#pragma unroll
        for (int o = 16; o; o >>= 1) q2 += __shfl_xor_sync(0xffffffffu, q2, o);
        float rstd = rsqrtf(q2 * (1.f / 96.f) + 1e-5f);
        XN[t * 104 + lane] =
            __float2bfloat16_rn(d0 * rstd * __ldg(&n1w[lane]) + __ldg(&n1b[lane]));
        XN[t * 104 + lane + 32] =
            __float2bfloat16_rn(d1 * rstd * __ldg(&n1w[lane + 32]) + __ldg(&n1b[lane + 32]));
        XN[t * 104 + lane + 64] =
            __float2bfloat16_rn(d2 * rstd * __ldg(&n1w[lane + 64]) + __ldg(&n1b[lane + 64]));
    }

    // ---- Q, K, V gemms (16x32 tiles) with cp.async staged weights ----
    for (int part = 0; part < 3; ++part) {
        for (int idx = tid; idx < 96 * 12; idx += 256) {
            int r = idx / 12, q = idx % 12;
            cpa16(W + r * 104 + q * 8, g_wqkv + part * 9216 + r * 96 + q * 8);
        }
        cpa_wait();
        __syncthreads();
        __nv_bfloat16* DST = (part == 0) ? Q : (part == 1) ? K : V;
        for (int mac = wid; mac < 21; mac += 8) {
            int mt = mac / 3, nt = mac % 3;
            int m0 = mt * 16, n0 = nt * 32;
            float c[4][4] = {};
            gemm16x32<6, 104, 104>(XN, W, m0, n0, lane, c);
#pragma unroll
            for (int nn = 0; nn < 4; ++nn) {
                int d = n0 + nn * 8 + 2 * t4;
                float b0 = __ldg(&qkv_b[part * 96 + d]);
                float b1 = __ldg(&qkv_b[part * 96 + d + 1]);
#pragma unroll
                for (int rh = 0; rh < 2; ++rh) {
                    int trow = m0 + g + rh * 8;
                    float v0 = c[nn][rh * 2]     + b0;
                    float v1 = c[nn][rh * 2 + 1] + b1;
                    if (trow >= 98) { v0 = 0.f; v1 = 0.f; }
                    if (part == 0) { v0 *= SCALE; v1 *= SCALE; }
                    st_bf2(DST + trow * 104 + d, v0, v1);
                }
            }
        }
        __syncthreads();
    }

    // ---- stage Wproj (overlaps flash attention below) ----
    for (int idx = tid; idx < 96 * 12; idx += 256) {
        int r = idx / 12, q = idx % 12;
        cpa16(W + r * 104 + q * 8, g_wproj + r * 96 + q * 8);
    }

    // ---- flash attention in registers ----
    const int l7 = lane & 7;
    for (int unit = wid; unit < 21; unit += 8) {
        int h = unit / 7, m0 = (unit % 7) * 16;
        const __nv_bfloat16* Qh = Q + h * 32;
        const __nv_bfloat16* Kh = K + h * 32;

        unsigned qa[2][4];
        {
            unsigned aA = sm_u32(Qh + (m0 + ((lane >> 3) & 1) * 8 + l7) * 104 +
                                 ((lane >> 4) & 1) * 8);
            ldsm4(aA,      qa[0][0], qa[0][1], qa[0][2], qa[0][3]);
            ldsm4(aA + 32, qa[1][0], qa[1][1], qa[1][2], qa[1][3]);
        }

        float s[7][2][4];
#pragma unroll
        for (int j = 0; j < 7; ++j) {
#pragma unroll
            for (int hf = 0; hf < 2; ++hf)
#pragma unroll
                for (int e = 0; e < 4; ++e) s[j][hf][e] = 0.f;
            unsigned aB = sm_u32(Kh + (j * 16 + ((lane >> 4) & 1) * 8 + l7) * 104 +
                                 ((lane >> 3) & 1) * 8);
#pragma unroll
            for (int ks = 0; ks < 2; ++ks) {
                unsigned b0, b1, b2, b3;
                ldsm4(aB + ks * 32, b0, b1, b2, b3);
                mmabf(s[j][0], qa[ks][0], qa[ks][1], qa[ks][2], qa[ks][3], b0, b1);
                mmabf(s[j][1], qa[ks][0], qa[ks][1], qa[ks][2], qa[ks][3], b2, b3);
            }
        }

        int i0 = m0 + g;     if (i0 > 97) i0 = 97;
        int i1 = m0 + g + 8; if (i1 > 97) i1 = 97;
        const __nv_bfloat16* bi0 = g_bias_bf + h * 9604 + i0 * 98;
        const __nv_bfloat16* bi1 = g_bias_bf + h * 9604 + i1 * 98;
        float mx0 = -1e30f, mx1 = -1e30f;
#pragma unroll
        for (int j = 0; j < 7; ++j) {
#pragma unroll
            for (int hf = 0; hf < 2; ++hf) {
                int col = 16 * j + 8 * hf + 2 * t4;
                if (col < 98) {
                    __nv_bfloat162 b0 = *reinterpret_cast<const __nv_bfloat162*>(bi0 + col);
                    __nv_bfloat162 b1 = *reinterpret_cast<const __nv_bfloat162*>(bi1 + col);
                    s[j][hf][0] += __bfloat162float(b0.x);
                    s[j][hf][1] += __bfloat162float(b0.y);
                    s[j][hf][2] += __bfloat162float(b1.x);
                    s[j][hf][3] += __bfloat162float(b1.y);
                    mx0 = fmaxf(mx0, fmaxf(s[j][hf][0], s[j][hf][1]));
                    mx1 = fmaxf(mx1, fmaxf(s[j][hf][2], s[j][hf][3]));
                } else {
                    s[j][hf][0] = -1e30f; s[j][hf][1] = -1e30f;
                    s[j][hf][2] = -1e30f; s[j][hf][3] = -1e30f;
                }
            }
        }
        mx0 = fmaxf(mx0, __shfl_xor_sync(0xffffffffu, mx0, 1));
        mx0 = fmaxf(mx0, __shfl_xor_sync(0xffffffffu, mx0, 2));
        mx1 = fmaxf(mx1, __shfl_xor_sync(0xffffffffu, mx1, 1));
        mx1 = fmaxf(mx1, __shfl_xor_sync(0xffffffffu, mx1, 2));
        float sum0 = 0.f, sum1 = 0.f;
#pragma unroll
        for (int j = 0; j < 7; ++j)
#pragma unroll
            for (int hf = 0; hf < 2; ++hf) {
                s[j][hf][0] = __expf(s[j][hf][0] - mx0);
                s[j][hf][1] = __expf(s[j][hf][1] - mx0);
                s[j][hf][2] = __expf(s[j][hf][2] - mx1);
                s[j][hf][3] = __expf(s[j][hf][3] - mx1);
                sum0 += s[j][hf][0] + s[j][hf][1];
                sum1 += s[j][hf][2] + s[j][hf][3];
            }
        sum0 += __shfl_xor_sync(0xffffffffu, sum0, 1);
        sum0 += __shfl_xor_sync(0xffffffffu, sum0, 2);
        sum1 += __shfl_xor_sync(0xffffffffu, sum1, 1);
        sum1 += __shfl_xor_sync(0xffffffffu, sum1, 2);
        float r0 = __fdividef(1.f, sum0), r1 = __fdividef(1.f, sum1);

        unsigned pa[7][4];
#pragma unroll
        for (int j = 0; j < 7; ++j) {
            pa[j][0] = pack_bf2(s[j][0][0] * r0, s[j][0][1] * r0);
            pa[j][1] = pack_bf2(s[j][0][2] * r1, s[j][0][3] * r1);
            pa[j][2] = pack_bf2(s[j][1][0] * r0, s[j][1][1] * r0);
            pa[j][3] = pack_bf2(s[j][1][2] * r1, s[j][1][3] * r1);
        }

        float o[2][2][4] = {};
#pragma unroll
        for (int j = 0; j < 7; ++j) {
            unsigned vb = sm_u32(V + (j * 16 + ((lane >> 3) & 1) * 8 + l7) * 104 +
                                 h * 32 + ((lane >> 4) & 1) * 8);
            unsigned b0, b1, b2, b3;
            ldsm4t(vb, b0, b1, b2, b3);
            mmabf(o[0][0], pa[j][0], pa[j][1], pa[j][2], pa[j][3], b0, b1);
            mmabf(o[0][1], pa[j][0], pa[j][1], pa[j][2], pa[j][3], b2, b3);
            ldsm4t(vb + 32, b0, b1, b2, b3);
            mmabf(o[1][0], pa[j][0], pa[j][1], pa[j][2], pa[j][3], b0, b1);
            mmabf(o[1][1], pa[j][0], pa[j][1], pa[j][2], pa[j][3], b2, b3);
        }

#pragma unroll
        for (int nc = 0; nc < 2; ++nc)
#pragma unroll
            for (int hf = 0; hf < 2; ++hf) {
                int col = h * 32 + nc * 16 + hf * 8 + 2 * t4;
#pragma unroll
                for (int rh = 0; rh < 2; ++rh)
                    st_bf2(AO + (m0 + g + rh * 8) * 104 + col,
                           o[nc][hf][rh * 2], o[nc][hf][rh * 2 + 1]);
            }
    }
    cpa_wait();
    __syncthreads();

    // ---- proj (16x32 tiles) + bias + residual ----
    for (int mac = wid; mac < 21; mac += 8) {
        int mt = mac / 3, nt = mac % 3;
        int m0 = mt * 16, n0 = nt * 32;
        float c[4][4] = {};
        gemm16x32<6, 104, 104>(AO, W, m0, n0, lane, c);
#pragma unroll
        for (int nn = 0; nn < 4; ++nn) {
            int col = n0 + nn * 8 + 2 * t4;
            float pb0 = __ldg(&proj_b[col]), pb1 = __ldg(&proj_b[col + 1]);
#pragma unroll
            for (int rh = 0; rh < 2; ++rh) {
                int trow = m0 + g + rh * 8;
                if (trow < 98) {
                    int off = s_toff[trow] + col;
                    float2 xr = *reinterpret_cast<const float2*>(&x[off]);
                    float2 o2;
                    o2.x = c[nn][rh * 2]     + pb0 + xr.x;
                    o2.y = c[nn][rh * 2 + 1] + pb1 + xr.y;
                    *reinterpret_cast<float2*>(&g_xmid[off]) = o2;
                }
            }
        }
    }
}

// ---------------- kernel 2 smem layout ----------------
#define M_X  0            // bf16 [128][104] = 26624
#define M_H  26624        // bf16 [128][104]
#define M_W1 53248        // bf16 [96][104]  = 19968
#define M_W2 73216        // bf16 [96][104]
#define SM2_BYTES 93184

__device__ __forceinline__ float gelu_exact(float v)
{
    return 0.5f * v * (1.f + erff(v * 0.70710678118654752f));
}

__global__ __launch_bounds__(384, 2)
void mlp_kernel(const float* __restrict__ n2w, const float* __restrict__ n2b,
                const float* __restrict__ fc1_b, const float* __restrict__ fc2_b,
                float* __restrict__ out)
{
    extern __shared__ char smc[];
    __nv_bfloat16* X  = (__nv_bfloat16*)(smc + M_X);
    __nv_bfloat16* H  = (__nv_bfloat16*)(smc + M_H);
    __nv_bfloat16* W1 = (__nv_bfloat16*)(smc + M_W1);
    __nv_bfloat16* W2 = (__nv_bfloat16*)(smc + M_W2);

    const int tid = threadIdx.x;
    const int wid = tid >> 5, lane = tid & 31;
    const int g = lane >> 2, t4 = lane & 3;
    const int tbase = blockIdx.x * 128;

    // warp tile assignment: 12 warps -> 4m x 3n grid of 32x32 tiles
    const int mt = wid / 3, nt = wid % 3;
    const int m0 = mt * 32, n0 = nt * 32;

    // ---- LN2 -> X bf16 ----
    for (int t = wid; t < 128; t += 12) {
        const float* p = g_xmid + (tbase + t) * 96;
        float v0 = p[lane], v1 = p[lane + 32], v2 = p[lane + 64];
        float s = v0 + v1 + v2;
#pragma unroll
        for (int o = 16; o; o >>= 1) s += __shfl_xor_sync(0xffffffffu, s, o);
        float mean = s * (1.f / 96.f);
        float d0 = v0 - mean, d1 = v1 - mean, d2 = v2 - mean;
        float q2 = d0 * d0 + d1 * d1 + d2 * d2;
#pragma unroll
        for (int o = 16; o; o >>= 1) q2 += __shfl_xor_sync(0xffffffffu, q2, o);
        float rstd = rsqrtf(q2 * (1.f / 96.f) + 1e-5f);
        X[t * 104 + lane] =
            __float2bfloat16_rn(d0 * rstd * __ldg(&n2w[lane]) + __ldg(&n2b[lane]));
        X[t * 104 + lane + 32] =
            __float2bfloat16_rn(d1 * rstd * __ldg(&n2w[lane + 32]) + __ldg(&n2b[lane + 32]));
        X[t * 104 + lane + 64] =
            __float2bfloat16_rn(d2 * rstd * __ldg(&n2w[lane + 64]) + __ldg(&n2b[lane + 64]));
    }

    float c2[2][4][4] = {};   // persistent fc2 accumulators (one 32x32 tile)

    for (int ch = 0; ch < 4; ++ch) {
        __syncthreads();   // X ready / previous chunk's readers done
        for (int idx = tid; idx < 96 * 12; idx += 384) {
            int r = idx / 12, q = idx % 12;
            cpa16(W1 + r * 104 + q * 8, g_fc1 + (ch * 96 + r) * 96 + q * 8);
            cpa16(W2 + r * 104 + q * 8, g_fc2 + r * 384 + ch * 96 + q * 8);
        }
        cpa_wait();
        __syncthreads();

        // fc1 tile (32 tokens x 32 hidden) + GELU -> H
        {
            float c[2][4][4] = {};
            gemm32x32<6, 104, 104>(X, W1, m0, n0, lane, c);
#pragma unroll
            for (int mf = 0; mf < 2; ++mf)
#pragma unroll
                for (int nn = 0; nn < 4; ++nn) {
                    int col = n0 + nn * 8 + 2 * t4;
                    float b0 = __ldg(&fc1_b[ch * 96 + col]);
                    float b1 = __ldg(&fc1_b[ch * 96 + col + 1]);
#pragma unroll
                    for (int rh = 0; rh < 2; ++rh)
                        st_bf2(H + (m0 + mf * 16 + g + rh * 8) * 104 + col,
                               gelu_exact(c[mf][nn][rh * 2] + b0),
                               gelu_exact(c[mf][nn][rh * 2 + 1] + b1));
                }
        }
        __syncthreads();

        // fc2 tile accumulate (32 tokens x 32 out)
        gemm32x32<6, 104, 104>(H, W2, m0, n0, lane, c2);
    }

    // ---- epilogue: bias + residual -> out ----
#pragma unroll
    for (int mf = 0; mf < 2; ++mf)
#pragma unroll
        for (int nn = 0; nn < 4; ++nn) {
            int col = n0 + nn * 8 + 2 * t4;
            float b0 = __ldg(&fc2_b[col]), b1 = __ldg(&fc2_b[col + 1]);
#pragma unroll
            for (int rh = 0; rh < 2; ++rh) {
                int off = (tbase + m0 + mf * 16 + g + rh * 8) * 96 + col;
                float2 xr = *reinterpret_cast<const float2*>(&g_xmid[off]);
                float2 o2;
                o2.x = c2[mf][nn][rh * 2]     + b0 + xr.x;
                o2.y = c2[mf][nn][rh * 2 + 1] + b1 + xr.y;
                *reinterpret_cast<float2*>(&out[off]) = o2;
            }
        }
}

// ---------------- launch ----------------
extern "C" void kernel_launch(void* const* d_in, const int* in_sizes, int n_in,
                              void* d_out, int out_size)
{
    const float* x      = (const float*)d_in[0];
    const float* n1w    = (const float*)d_in[1];
    const float* n1b    = (const float*)d_in[2];
    const float* qkv_w  = (const float*)d_in[3];
    const float* qkv_b  = (const float*)d_in[4];
    const float* proj_w = (const float*)d_in[5];
    const float* proj_b = (const float*)d_in[6];
    const float* rpb    = (const float*)d_in[7];
    const float* n2w    = (const float*)d_in[8];
    const float* n2b    = (const float*)d_in[9];
    const float* fc1_w  = (const float*)d_in[10];
    const float* fc1_b  = (const float*)d_in[11];
    const float* fc2_w  = (const float*)d_in[12];
    const float* fc2_b  = (const float*)d_in[13];
    float* out = (float*)d_out;

    cudaFuncSetAttribute(attn_kernel, cudaFuncAttributeMaxDynamicSharedMemorySize, SM1_BYTES);
    cudaFuncSetAttribute(mlp_kernel,  cudaFuncAttributeMaxDynamicSharedMemorySize, SM2_BYTES);

    prep_kernel<<<128, 256>>>(qkv_w, proj_w, fc1_w, fc2_w, rpb);
    attn_kernel<<<NWIN, 256, SM1_BYTES>>>(x, n1w, n1b, qkv_b, proj_b);
    mlp_kernel<<<NTOKENS / 128, 384, SM2_BYTES>>>(n2w, n2b, fc1_b, fc2_b, out);
}

// round 7
// speedup vs baseline: 7.9324x; 1.1024x over previous
#include <cuda_runtime.h>
#include <cuda_bf16.h>
#include <math.h>

#define NWIN    2048
#define NTOKENS 200704
#define XELEMS  (NTOKENS * 96)
#define SCALEL  0.25503472f      // (1/sqrt(32)) * log2(e)

// ---------------- device scratch ----------------
__device__ float g_xmid[XELEMS];
__device__ __nv_bfloat16 g_bias_bf[3 * 98 * 112];  // [h][i][j], *log2e, pad j>=98 = -30000
__device__ __nv_bfloat16 g_wqkv[288 * 96];
__device__ __nv_bfloat16 g_wproj[96 * 96];
__device__ __nv_bfloat16 g_fc1[384 * 96];
__device__ __nv_bfloat16 g_fc2[96 * 384];

// ---------------- prep ----------------
__global__ void prep_kernel(const float* __restrict__ qkv_w,
                            const float* __restrict__ proj_w,
                            const float* __restrict__ fc1_w,
                            const float* __restrict__ fc2_w,
                            const float* __restrict__ rpb)
{
    int tid = blockIdx.x * blockDim.x + threadIdx.x;
    int stride = gridDim.x * blockDim.x;
    for (int i = tid; i < 288 * 96; i += stride) g_wqkv[i]  = __float2bfloat16_rn(qkv_w[i]);
    for (int i = tid; i < 96 * 96;  i += stride) g_wproj[i] = __float2bfloat16_rn(proj_w[i]);
    for (int i = tid; i < 384 * 96; i += stride) g_fc1[i]   = __float2bfloat16_rn(fc1_w[i]);
    for (int i = tid; i < 96 * 384; i += stride) g_fc2[i]   = __float2bfloat16_rn(fc2_w[i]);
    for (int idx = tid; idx < 3 * 98 * 112; idx += stride) {
        int h = idx / (98 * 112);
        int r = idx - h * 98 * 112;
        int n = r / 112, m = r - n * 112;
        float v;
        if (m < 98) {
            int nd = n / 49, nh = (n % 49) / 7, nw = n % 7;
            int md = m / 49, mh = (m % 49) / 7, mw = m % 7;
            int rel = (nd - md + 1) * 169 + (nh - mh + 6) * 13 + (nw - mw + 6);
            v = rpb[rel * 3 + h] * 1.4426950408889634f;
        } else {
            v = -30000.f;
        }
        g_bias_bf[idx] = __float2bfloat16_rn(v);
    }
}

// ---------------- helpers ----------------
__device__ __forceinline__ unsigned sm_u32(const void* p)
{
    return (unsigned)__cvta_generic_to_shared(p);
}

__device__ __forceinline__ void cpa16(void* dst, const void* src)
{
    asm volatile("cp.async.cg.shared.global [%0], [%1], 16;\n"
                 :: "r"(sm_u32(dst)), "l"(src));
}

#define CPA_COMMIT() asm volatile("cp.async.commit_group;\n" ::: "memory")
#define CPA_WAIT0()  asm volatile("cp.async.wait_group 0;\n" ::: "memory")

__device__ __forceinline__ float ex2f(float x)
{
    float r;
    asm("ex2.approx.f32 %0, %1;\n" : "=f"(r) : "f"(x));
    return r;
}

__device__ __forceinline__ void ldsm4(unsigned addr, unsigned& r0, unsigned& r1,
                                      unsigned& r2, unsigned& r3)
{
    asm volatile("ldmatrix.sync.aligned.m8n8.x4.shared.b16 {%0,%1,%2,%3}, [%4];\n"
                 : "=r"(r0), "=r"(r1), "=r"(r2), "=r"(r3) : "r"(addr));
}

__device__ __forceinline__ void ldsm4t(unsigned addr, unsigned& r0, unsigned& r1,
                                       unsigned& r2, unsigned& r3)
{
    asm volatile("ldmatrix.sync.aligned.m8n8.x4.trans.shared.b16 {%0,%1,%2,%3}, [%4];\n"
                 : "=r"(r0), "=r"(r1), "=r"(r2), "=r"(r3) : "r"(addr));
}

__device__ __forceinline__ void mmabf(float* c, unsigned a0, unsigned a1, unsigned a2,
                                      unsigned a3, unsigned b0, unsigned b1)
{
    asm volatile(
        "mma.sync.aligned.m16n8k16.row.col.f32.bf16.bf16.f32 "
        "{%0,%1,%2,%3}, {%4,%5,%6,%7}, {%8,%9}, {%0,%1,%2,%3};\n"
        : "+f"(c[0]), "+f"(c[1]), "+f"(c[2]), "+f"(c[3])
        : "r"(a0), "r"(a1), "r"(a2), "r"(a3), "r"(b0), "r"(b1));
}

template <int KSTEPS, int LDA, int LDB>
__device__ __forceinline__ void gemm16x32(const __nv_bfloat16* __restrict__ A,
                                          const __nv_bfloat16* __restrict__ B,
                                          int m0, int n0, int lane, float c[4][4])
{
    const int l7 = lane & 7, s8 = (lane >> 3) & 1, s16 = (lane >> 4) & 1;
    unsigned aA  = sm_u32(A + (m0 + s8 * 8 + l7) * LDA + s16 * 8);
    unsigned aB0 = sm_u32(B + (n0 + s16 * 8 + l7) * LDB + s8 * 8);
    unsigned aB1 = aB0 + 16 * LDB * 2;
#pragma unroll
    for (int ks = 0; ks < KSTEPS; ++ks) {
        unsigned a0, a1, a2, a3, b0, b1, b2, b3;
        ldsm4(aA + ks * 32, a0, a1, a2, a3);
        ldsm4(aB0 + ks * 32, b0, b1, b2, b3);
        mmabf(c[0], a0, a1, a2, a3, b0, b1);
        mmabf(c[1], a0, a1, a2, a3, b2, b3);
        ldsm4(aB1 + ks * 32, b0, b1, b2, b3);
        mmabf(c[2], a0, a1, a2, a3, b0, b1);
        mmabf(c[3], a0, a1, a2, a3, b2, b3);
    }
}

template <int KSTEPS, int LDA, int LDB>
__device__ __forceinline__ void gemm32x32(const __nv_bfloat16* __restrict__ A,
                                          const __nv_bfloat16* __restrict__ B,
                                          int m0, int n0, int lane, float c[2][4][4])
{
    const int l7 = lane & 7, s8 = (lane >> 3) & 1, s16 = (lane >> 4) & 1;
    unsigned aA0 = sm_u32(A + (m0 + s8 * 8 + l7) * LDA + s16 * 8);
    unsigned aA1 = aA0 + 16 * LDA * 2;
    unsigned aB0 = sm_u32(B + (n0 + s16 * 8 + l7) * LDB + s8 * 8);
    unsigned aB1 = aB0 + 16 * LDB * 2;
#pragma unroll
    for (int ks = 0; ks < KSTEPS; ++ks) {
        unsigned a00, a01, a02, a03, a10, a11, a12, a13, b0, b1, b2, b3;
        ldsm4(aA0 + ks * 32, a00, a01, a02, a03);
        ldsm4(aA1 + ks * 32, a10, a11, a12, a13);
        ldsm4(aB0 + ks * 32, b0, b1, b2, b3);
        mmabf(c[0][0], a00, a01, a02, a03, b0, b1);
        mmabf(c[0][1], a00, a01, a02, a03, b2, b3);
        mmabf(c[1][0], a10, a11, a12, a13, b0, b1);
        mmabf(c[1][1], a10, a11, a12, a13, b2, b3);
        ldsm4(aB1 + ks * 32, b0, b1, b2, b3);
        mmabf(c[0][2], a00, a01, a02, a03, b0, b1);
        mmabf(c[0][3], a00, a01, a02, a03, b2, b3);
        mmabf(c[1][2], a10, a11, a12, a13, b0, b1);
        mmabf(c[1][3], a10, a11, a12, a13, b2, b3);
    }
}

__device__ __forceinline__ void st_bf2(__nv_bfloat16* p, float x, float y)
{
    __nv_bfloat162 v = __floats2bfloat162_rn(x, y);
    *reinterpret_cast<__nv_bfloat162*>(p) = v;
}

__device__ __forceinline__ unsigned pack_bf2(float x, float y)
{
    __nv_bfloat162 v = __floats2bfloat162_rn(x, y);
    return *reinterpret_cast<unsigned*>(&v);
}

// stage a 96x96 bf16 weight block (row stride 96 in gmem) into smem stride 104
__device__ __forceinline__ void stage_w(__nv_bfloat16* dst, const __nv_bfloat16* src,
                                        int tid, int nthr)
{
    for (int idx = tid; idx < 96 * 12; idx += nthr) {
        int r = idx / 12, q = idx % 12;
        cpa16(dst + r * 104 + q * 8, src + r * 96 + q * 8);
    }
}

// ---------------- kernel 1 smem layout (bytes) ----------------
#define A_XN 0          // XN, later AO
#define A_Q  23296
#define A_K  46592
#define A_VW 69888      // Wk staging, later V
#define A_W  93184      // Wq -> Wv -> Wproj
#define SM1_BYTES 113152

__device__ __forceinline__ void qkv_part(const __nv_bfloat16* XN, const __nv_bfloat16* W,
                                         __nv_bfloat16* DST, const float* qkv_b,
                                         int bias_off, float scale,
                                         int wid, int lane, int g, int t4)
{
    for (int mac = wid; mac < 21; mac += 8) {
        int mt = mac / 3, nt = mac % 3;
        int m0 = mt * 16, n0 = nt * 32;
        float c[4][4] = {};
        gemm16x32<6, 104, 104>(XN, W, m0, n0, lane, c);
#pragma unroll
        for (int nn = 0; nn < 4; ++nn) {
            int d = n0 + nn * 8 + 2 * t4;
            float b0 = __ldg(&qkv_b[bias_off + d]);
            float b1 = __ldg(&qkv_b[bias_off + d + 1]);
#pragma unroll
            for (int rh = 0; rh < 2; ++rh) {
                int trow = m0 + g + rh * 8;
                float v0 = (c[nn][rh * 2]     + b0) * scale;
                float v1 = (c[nn][rh * 2 + 1] + b1) * scale;
                if (trow >= 98) { v0 = 0.f; v1 = 0.f; }
                st_bf2(DST + trow * 104 + d, v0, v1);
            }
        }
    }
}

__global__ __launch_bounds__(256, 2)
void attn_kernel(const float* __restrict__ x,
                 const float* __restrict__ n1w, const float* __restrict__ n1b,
                 const float* __restrict__ qkv_b, const float* __restrict__ proj_b)
{
    extern __shared__ char smc[];
    __nv_bfloat16* XN = (__nv_bfloat16*)(smc + A_XN);
    __nv_bfloat16* AO = (__nv_bfloat16*)(smc + A_XN);
    __nv_bfloat16* Q  = (__nv_bfloat16*)(smc + A_Q);
    __nv_bfloat16* K  = (__nv_bfloat16*)(smc + A_K);
    __nv_bfloat16* VW = (__nv_bfloat16*)(smc + A_VW);  // Wk, then V
    __nv_bfloat16* W  = (__nv_bfloat16*)(smc + A_W);
    __shared__ int s_toff[98];

    const int tid = threadIdx.x;
    const int wid = tid >> 5, lane = tid & 31;
    const int g = lane >> 2, t4 = lane & 3;

    // prefetch Wq (hidden behind toff/LN)
    stage_w(W, g_wqkv, tid, 256);
    CPA_COMMIT();

    const int widx = blockIdx.x;
    const int b = widx >> 8;
    const int rr = widx & 255;
    const int dblk = rr >> 6, hblk = (rr >> 3) & 7, wblk = rr & 7;
    if (tid < 98) {
        int wd = (tid >= 49);
        int rem = tid - wd * 49;
        int wh = rem / 7, ww = rem - wh * 7;
        s_toff[tid] = (((b * 8 + dblk * 2 + wd) * 56 + hblk * 7 + wh) * 56 + wblk * 7 + ww) * 96;
    }
    for (int i = tid; i < 14 * 52; i += 256)
        reinterpret_cast<unsigned*>(XN + 98 * 104)[i] = 0u;
    __syncthreads();

    // ---- LN1 -> XN bf16 [t][c] ----
    for (int t = wid; t < 98; t += 8) {
        int off = s_toff[t];
        float v0 = x[off + lane];
        float v1 = x[off + lane + 32];
        float v2 = x[off + lane + 64];
        float s = v0 + v1 + v2;
#pragma unroll
        for (int o = 16; o; o >>= 1) s += __shfl_xor_sync(0xffffffffu, s, o);
        float mean = s * (1.f / 96.f);
        float d0 = v0 - mean, d1 = v1 - mean, d2 = v2 - mean;
        float q2 = d0 * d0 + d1 * d1 + d2 * d2;
#pragma unroll
        for (int o = 16; o; o >>= 1) q2 += __shfl_xor_sync(0xffffffffu, q2, o);
        float rstd = rsqrtf(q2 * (1.f / 96.f) + 1e-5f);
        XN[t * 104 + lane] =
            __float2bfloat16_rn(d0 * rstd * __ldg(&n1w[lane]) + __ldg(&n1b[lane]));
        XN[t * 104 + lane + 32] =
            __float2bfloat16_rn(d1 * rstd * __ldg(&n1w[lane + 32]) + __ldg(&n1b[lane + 32]));
        XN[t * 104 + lane + 64] =
            __float2bfloat16_rn(d2 * rstd * __ldg(&n1w[lane + 64]) + __ldg(&n1b[lane + 64]));
    }
    CPA_WAIT0();
    __syncthreads();                 // XN + Wq ready

    stage_w(VW, g_wqkv + 9216, tid, 256);   // Wk (hidden behind Q gemm)
    CPA_COMMIT();
    qkv_part(XN, W, Q, qkv_b, 0, SCALEL, wid, lane, g, t4);
    CPA_WAIT0();
    __syncthreads();                 // Q + Wk ready

    stage_w(W, g_wqkv + 18432, tid, 256);   // Wv (hidden behind K gemm)
    CPA_COMMIT();
    qkv_part(XN, VW, K, qkv_b, 96, 1.f, wid, lane, g, t4);
    CPA_WAIT0();
    __syncthreads();                 // K + Wv ready

    qkv_part(XN, W, VW, qkv_b, 192, 1.f, wid, lane, g, t4);  // V into VW
    __syncthreads();                 // V ready, W free

    stage_w(W, g_wproj, tid, 256);   // Wproj (hidden behind flash)
    CPA_COMMIT();

    // ---- flash attention in registers ----
    const __nv_bfloat16* V = VW;
    const int l7 = lane & 7;
    for (int unit = wid; unit < 21; unit += 8) {
        int h = unit / 7, m0 = (unit % 7) * 16;
        const __nv_bfloat16* Qh = Q + h * 32;
        const __nv_bfloat16* Kh = K + h * 32;

        unsigned qa[2][4];
        {
            unsigned aA = sm_u32(Qh + (m0 + ((lane >> 3) & 1) * 8 + l7) * 104 +
                                 ((lane >> 4) & 1) * 8);
            ldsm4(aA,      qa[0][0], qa[0][1], qa[0][2], qa[0][3]);
            ldsm4(aA + 32, qa[1][0], qa[1][1], qa[1][2], qa[1][3]);
        }

        float s[7][2][4];
#pragma unroll
        for (int j = 0; j < 7; ++j) {
#pragma unroll
            for (int hf = 0; hf < 2; ++hf)
#pragma unroll
                for (int e = 0; e < 4; ++e) s[j][hf][e] = 0.f;
            unsigned aB = sm_u32(Kh + (j * 16 + ((lane >> 4) & 1) * 8 + l7) * 104 +
                                 ((lane >> 3) & 1) * 8);
#pragma unroll
            for (int ks = 0; ks < 2; ++ks) {
                unsigned b0, b1, b2, b3;
                ldsm4(aB + ks * 32, b0, b1, b2, b3);
                mmabf(s[j][0], qa[ks][0], qa[ks][1], qa[ks][2], qa[ks][3], b0, b1);
                mmabf(s[j][1], qa[ks][0], qa[ks][1], qa[ks][2], qa[ks][3], b2, b3);
            }
        }

        // branchless bias + max (bias pre-scaled by log2e; pad cols = -30000)
        int i0 = m0 + g;     if (i0 > 97) i0 = 97;
        int i1 = m0 + g + 8; if (i1 > 97) i1 = 97;
        const __nv_bfloat16* bi0 = g_bias_bf + h * 10976 + i0 * 112;
        const __nv_bfloat16* bi1 = g_bias_bf + h * 10976 + i1 * 112;
        float mx0 = -1e30f, mx1 = -1e30f;
#pragma unroll
        for (int j = 0; j < 7; ++j) {
#pragma unroll
            for (int hf = 0; hf < 2; ++hf) {
                int col = 16 * j + 8 * hf + 2 * t4;
                __nv_bfloat162 b0 = *reinterpret_cast<const __nv_bfloat162*>(bi0 + col);
                __nv_bfloat162 b1 = *reinterpret_cast<const __nv_bfloat162*>(bi1 + col);
                s[j][hf][0] += __bfloat162float(b0.x);
                s[j][hf][1] += __bfloat162float(b0.y);
                s[j][hf][2] += __bfloat162float(b1.x);
                s[j][hf][3] += __bfloat162float(b1.y);
                mx0 = fmaxf(mx0, fmaxf(s[j][hf][0], s[j][hf][1]));
                mx1 = fmaxf(mx1, fmaxf(s[j][hf][2], s[j][hf][3]));
            }
        }
        mx0 = fmaxf(mx0, __shfl_xor_sync(0xffffffffu, mx0, 1));
        mx0 = fmaxf(mx0, __shfl_xor_sync(0xffffffffu, mx0, 2));
        mx1 = fmaxf(mx1, __shfl_xor_sync(0xffffffffu, mx1, 1));
        mx1 = fmaxf(mx1, __shfl_xor_sync(0xffffffffu, mx1, 2));
        float sum0 = 0.f, sum1 = 0.f;
#pragma unroll
        for (int j = 0; j < 7; ++j)
#pragma unroll
            for (int hf = 0; hf < 2; ++hf) {
                s[j][hf][0] = ex2f(s[j][hf][0] - mx0);
                s[j][hf][1] = ex2f(s[j][hf][1] - mx0);
                s[j][hf][2] = ex2f(s[j][hf][2] - mx1);
                s[j][hf][3] = ex2f(s[j][hf][3] - mx1);
                sum0 += s[j][hf][0] + s[j][hf][1];
                sum1 += s[j][hf][2] + s[j][hf][3];
            }
        sum0 += __shfl_xor_sync(0xffffffffu, sum0, 1);
        sum0 += __shfl_xor_sync(0xffffffffu, sum0, 2);
        sum1 += __shfl_xor_sync(0xffffffffu, sum1, 1);
        sum1 += __shfl_xor_sync(0xffffffffu, sum1, 2);
        float r0 = __fdividef(1.f, sum0), r1 = __fdividef(1.f, sum1);

        unsigned pa[7][4];
#pragma unroll
        for (int j = 0; j < 7; ++j) {
            pa[j][0] = pack_bf2(s[j][0][0] * r0, s[j][0][1] * r0);
            pa[j][1] = pack_bf2(s[j][0][2] * r1, s[j][0][3] * r1);
            pa[j][2] = pack_bf2(s[j][1][0] * r0, s[j][1][1] * r0);
            pa[j][3] = pack_bf2(s[j][1][2] * r1, s[j][1][3] * r1);
        }

        float o[2][2][4] = {};
#pragma unroll
        for (int j = 0; j < 7; ++j) {
            unsigned vb = sm_u32(V + (j * 16 + ((lane >> 3) & 1) * 8 + l7) * 104 +
                                 h * 32 + ((lane >> 4) & 1) * 8);
            unsigned b0, b1, b2, b3;
            ldsm4t(vb, b0, b1, b2, b3);
            mmabf(o[0][0], pa[j][0], pa[j][1], pa[j][2], pa[j][3], b0, b1);
            mmabf(o[0][1], pa[j][0], pa[j][1], pa[j][2], pa[j][3], b2, b3);
            ldsm4t(vb + 32, b0, b1, b2, b3);
            mmabf(o[1][0], pa[j][0], pa[j][1], pa[j][2], pa[j][3], b0, b1);
            mmabf(o[1][1], pa[j][0], pa[j][1], pa[j][2], pa[j][3], b2, b3);
        }

#pragma unroll
        for (int nc = 0; nc < 2; ++nc)
#pragma unroll
            for (int hf = 0; hf < 2; ++hf) {
                int col = h * 32 + nc * 16 + hf * 8 + 2 * t4;
#pragma unroll
                for (int rh = 0; rh < 2; ++rh)
                    st_bf2(AO + (m0 + g + rh * 8) * 104 + col,
                           o[nc][hf][rh * 2], o[nc][hf][rh * 2 + 1]);
            }
    }
    CPA_WAIT0();
    __syncthreads();                 // AO + Wproj ready

    // ---- proj + bias + residual ----
    for (int mac = wid; mac < 21; mac += 8) {
        int mt = mac / 3, nt = mac % 3;
        int m0 = mt * 16, n0 = nt * 32;
        float c[4][4] = {};
        gemm16x32<6, 104, 104>(AO, W, m0, n0, lane, c);
#pragma unroll
        for (int nn = 0; nn < 4; ++nn) {
            int col = n0 + nn * 8 + 2 * t4;
            float pb0 = __ldg(&proj_b[col]), pb1 = __ldg(&proj_b[col + 1]);
#pragma unroll
            for (int rh = 0; rh < 2; ++rh) {
                int trow = m0 + g + rh * 8;
                if (trow < 98) {
                    int off = s_toff[trow] + col;
                    float2 xr = *reinterpret_cast<const float2*>(&x[off]);
                    float2 o2;
                    o2.x = c[nn][rh * 2]     + pb0 + xr.x;
                    o2.y = c[nn][rh * 2 + 1] + pb1 + xr.y;
                    *reinterpret_cast<float2*>(&g_xmid[off]) = o2;
                }
            }
        }
    }
}

// ---------------- kernel 2 ----------------
#define M_X   0            // bf16 [128][104] = 26624
#define M_H   26624        // bf16 [128][104]
#define M_W1  53248        // bf16 [96][104]  = 19968
#define M_W2A 73216
#define M_W2B 93184
#define SM2_BYTES 113152

__device__ __forceinline__ float gelu_fast(float x)
{
    // tanh-form GELU in sigmoid/exp2 shape; deviation << bf16 quantization of h
    float t = x * x;
    float z = x * fmaf(0.10294322f, t, 2.30220781f);
    return __fdividef(x, 1.f + ex2f(-z));
}

__global__ __launch_bounds__(384, 2)
void mlp_kernel(const float* __restrict__ n2w, const float* __restrict__ n2b,
                const float* __restrict__ fc1_b, const float* __restrict__ fc2_b,
                float* __restrict__ out)
{
    extern __shared__ char smc[];
    __nv_bfloat16* X  = (__nv_bfloat16*)(smc + M_X);
    __nv_bfloat16* H  = (__nv_bfloat16*)(smc + M_H);
    __nv_bfloat16* W1 = (__nv_bfloat16*)(smc + M_W1);
    __nv_bfloat16* W2buf[2] = { (__nv_bfloat16*)(smc + M_W2A), (__nv_bfloat16*)(smc + M_W2B) };

    const int tid = threadIdx.x;
    const int wid = tid >> 5, lane = tid & 31;
    const int g = lane >> 2, t4 = lane & 3;
    const int tbase = blockIdx.x * 128;

    const int mt = wid / 3, nt = wid % 3;
    const int m0 = mt * 32, n0 = nt * 32;

    // preload chunk-0 weights (hidden behind LN)
    stage_w(W1, g_fc1, tid, 384);
    for (int idx = tid; idx < 96 * 12; idx += 384) {
        int r = idx / 12, q = idx % 12;
        cpa16(W2buf[0] + r * 104 + q * 8, g_fc2 + r * 384 + q * 8);
    }
    CPA_COMMIT();

    // ---- LN2 -> X bf16 ----
    for (int t = wid; t < 128; t += 12) {
        const float* p = g_xmid + (tbase + t) * 96;
        float v0 = p[lane], v1 = p[lane + 32], v2 = p[lane + 64];
        float s = v0 + v1 + v2;
#pragma unroll
        for (int o = 16; o; o >>= 1) s += __shfl_xor_sync(0xffffffffu, s, o);
        float mean = s * (1.f / 96.f);
        float d0 = v0 - mean, d1 = v1 - mean, d2 = v2 - mean;
        float q2 = d0 * d0 + d1 * d1 + d2 * d2;
#pragma unroll
        for (int o = 16; o; o >>= 1) q2 += __shfl_xor_sync(0xffffffffu, q2, o);
        float rstd = rsqrtf(q2 * (1.f / 96.f) + 1e-5f);
        X[t * 104 + lane] =
            __float2bfloat16_rn(d0 * rstd * __ldg(&n2w[lane]) + __ldg(&n2b[lane]));
        X[t * 104 + lane + 32] =
            __float2bfloat16_rn(d1 * rstd * __ldg(&n2w[lane + 32]) + __ldg(&n2b[lane + 32]));
        X[t * 104 + lane + 64] =
            __float2bfloat16_rn(d2 * rstd * __ldg(&n2w[lane + 64]) + __ldg(&n2b[lane + 64]));
    }

    float c2[2][4][4] = {};   // persistent fc2 accumulators

    for (int ch = 0; ch < 4; ++ch) {
        CPA_WAIT0();
        __syncthreads();           // W1(ch), W2(ch), X/H deps all ready

        if (ch < 3) {              // prefetch W2(ch+1) into the idle buffer
            for (int idx = tid; idx < 96 * 12; idx += 384) {
                int r = idx / 12, q = idx % 12;
                cpa16(W2buf[(ch + 1) & 1] + r * 104 + q * 8,
                      g_fc2 + r * 384 + (ch + 1) * 96 + q * 8);
            }
            CPA_COMMIT();
        }

        // fc1 tile + GELU -> H
        {
            float c[2][4][4] = {};
            gemm32x32<6, 104, 104>(X, W1, m0, n0, lane, c);
#pragma unroll
            for (int mf = 0; mf < 2; ++mf)
#pragma unroll
                for (int nn = 0; nn < 4; ++nn) {
                    int col = n0 + nn * 8 + 2 * t4;
                    float b0 = __ldg(&fc1_b[ch * 96 + col]);
                    float b1 = __ldg(&fc1_b[ch * 96 + col + 1]);
#pragma unroll
                    for (int rh = 0; rh < 2; ++rh)
                        st_bf2(H + (m0 + mf * 16 + g + rh * 8) * 104 + col,
                               gelu_fast(c[mf][nn][rh * 2] + b0),
                               gelu_fast(c[mf][nn][rh * 2 + 1] + b1));
                }
        }
        __syncthreads();           // H ready, W1 free

        if (ch < 3) {              // prefetch W1(ch+1) (hidden behind fc2)
            stage_w(W1, g_fc1 + (ch + 1) * 96 * 96, tid, 384);
            CPA_COMMIT();
        }

        // fc2 tile accumulate
        gemm32x32<6, 104, 104>(H, W2buf[ch & 1], m0, n0, lane, c2);
    }

    // ---- epilogue: bias + residual -> out ----
#pragma unroll
    for (int mf = 0; mf < 2; ++mf)
#pragma unroll
        for (int nn = 0; nn < 4; ++nn) {
            int col = n0 + nn * 8 + 2 * t4;
            float b0 = __ldg(&fc2_b[col]), b1 = __ldg(&fc2_b[col + 1]);
#pragma unroll
            for (int rh = 0; rh < 2; ++rh) {
                int off = (tbase + m0 + mf * 16 + g + rh * 8) * 96 + col;
                float2 xr = *reinterpret_cast<const float2*>(&g_xmid[off]);
                float2 o2;
                o2.x = c2[mf][nn][rh * 2]     + b0 + xr.x;
                o2.y = c2[mf][nn][rh * 2 + 1] + b1 + xr.y;
                *reinterpret_cast<float2*>(&out[off]) = o2;
            }
        }
}

// ---------------- launch ----------------
extern "C" void kernel_launch(void* const* d_in, const int* in_sizes, int n_in,
                              void* d_out, int out_size)
{
    const float* x      = (const float*)d_in[0];
    const float* n1w    = (const float*)d_in[1];
    const float* n1b    = (const float*)d_in[2];
    const float* qkv_w  = (const float*)d_in[3];
    const float* qkv_b  = (const float*)d_in[4];
    const float* proj_w = (const float*)d_in[5];
    const float* proj_b = (const float*)d_in[6];
    const float* rpb    = (const float*)d_in[7];
    const float* n2w    = (const float*)d_in[8];
    const float* n2b    = (const float*)d_in[9];
    const float* fc1_w  = (const float*)d_in[10];
    const float* fc1_b  = (const float*)d_in[11];
    const float* fc2_w  = (const float*)d_in[12];
    const float* fc2_b  = (const float*)d_in[13];
    float* out = (float*)d_out;

    cudaFuncSetAttribute(attn_kernel, cudaFuncAttributeMaxDynamicSharedMemorySize, SM1_BYTES);
    cudaFuncSetAttribute(mlp_kernel,  cudaFuncAttributeMaxDynamicSharedMemorySize, SM2_BYTES);

    prep_kernel<<<128, 256>>>(qkv_w, proj_w, fc1_w, fc2_w, rpb);
    attn_kernel<<<NWIN, 256, SM1_BYTES>>>(x, n1w, n1b, qkv_b, proj_b);
    mlp_kernel<<<NTOKENS / 128, 384, SM2_BYTES>>>(n2w, n2b, fc1_b, fc2_b, out);
}

// round 8
// speedup vs baseline: 8.1762x; 1.0307x over previous
#include <cuda_runtime.h>
#include <cuda_bf16.h>
#include <math.h>

#define NWIN    2048
#define NTOKENS 200704
#define XELEMS  (NTOKENS * 96)
#define SCALEL  0.25503472f      // (1/sqrt(32)) * log2(e)

// ---------------- device scratch ----------------
__device__ float g_xmid[XELEMS];
__device__ __nv_bfloat16 g_bias_bf[3 * 98 * 112];  // [h][i][j], *log2e, pad j>=98 = -30000
__device__ __nv_bfloat16 g_wqkv[288 * 96];
__device__ __nv_bfloat16 g_wproj[96 * 96];
__device__ __nv_bfloat16 g_fc1[384 * 96];
__device__ __nv_bfloat16 g_fc2[96 * 384];

// ---------------- prep ----------------
__global__ void prep_kernel(const float* __restrict__ qkv_w,
                            const float* __restrict__ proj_w,
                            const float* __restrict__ fc1_w,
                            const float* __restrict__ fc2_w,
                            const float* __restrict__ rpb)
{
    int tid = blockIdx.x * blockDim.x + threadIdx.x;
    int stride = gridDim.x * blockDim.x;
    for (int i = tid; i < 288 * 96; i += stride) g_wqkv[i]  = __float2bfloat16_rn(qkv_w[i]);
    for (int i = tid; i < 96 * 96;  i += stride) g_wproj[i] = __float2bfloat16_rn(proj_w[i]);
    for (int i = tid; i < 384 * 96; i += stride) g_fc1[i]   = __float2bfloat16_rn(fc1_w[i]);
    for (int i = tid; i < 96 * 384; i += stride) g_fc2[i]   = __float2bfloat16_rn(fc2_w[i]);
    for (int idx = tid; idx < 3 * 98 * 112; idx += stride) {
        int h = idx / (98 * 112);
        int r = idx - h * 98 * 112;
        int n = r / 112, m = r - n * 112;
        float v;
        if (m < 98) {
            int nd = n / 49, nh = (n % 49) / 7, nw = n % 7;
            int md = m / 49, mh = (m % 49) / 7, mw = m % 7;
            int rel = (nd - md + 1) * 169 + (nh - mh + 6) * 13 + (nw - mw + 6);
            v = rpb[rel * 3 + h] * 1.4426950408889634f;
        } else {
            v = -30000.f;
        }
        g_bias_bf[idx] = __float2bfloat16_rn(v);
    }
}

// ---------------- helpers ----------------
__device__ __forceinline__ unsigned sm_u32(const void* p)
{
    return (unsigned)__cvta_generic_to_shared(p);
}

__device__ __forceinline__ void cpa16(void* dst, const void* src)
{
    asm volatile("cp.async.cg.shared.global [%0], [%1], 16;\n"
                 :: "r"(sm_u32(dst)), "l"(src));
}

#define CPA_COMMIT() asm volatile("cp.async.commit_group;\n" ::: "memory")
#define CPA_WAIT0()  asm volatile("cp.async.wait_group 0;\n" ::: "memory")

__device__ __forceinline__ float ex2f(float x)
{
    float r;
    asm("ex2.approx.f32 %0, %1;\n" : "=f"(r) : "f"(x));
    return r;
}

__device__ __forceinline__ float tanhf_hw(float x)
{
    float r;
    asm("tanh.approx.f32 %0, %1;\n" : "=f"(r) : "f"(x));
    return r;
}

__device__ __forceinline__ void ldsm4(unsigned addr, unsigned& r0, unsigned& r1,
                                      unsigned& r2, unsigned& r3)
{
    asm volatile("ldmatrix.sync.aligned.m8n8.x4.shared.b16 {%0,%1,%2,%3}, [%4];\n"
                 : "=r"(r0), "=r"(r1), "=r"(r2), "=r"(r3) : "r"(addr));
}

__device__ __forceinline__ void ldsm4t(unsigned addr, unsigned& r0, unsigned& r1,
                                       unsigned& r2, unsigned& r3)
{
    asm volatile("ldmatrix.sync.aligned.m8n8.x4.trans.shared.b16 {%0,%1,%2,%3}, [%4];\n"
                 : "=r"(r0), "=r"(r1), "=r"(r2), "=r"(r3) : "r"(addr));
}

__device__ __forceinline__ void mmabf(float* c, unsigned a0, unsigned a1, unsigned a2,
                                      unsigned a3, unsigned b0, unsigned b1)
{
    asm volatile(
        "mma.sync.aligned.m16n8k16.row.col.f32.bf16.bf16.f32 "
        "{%0,%1,%2,%3}, {%4,%5,%6,%7}, {%8,%9}, {%0,%1,%2,%3};\n"
        : "+f"(c[0]), "+f"(c[1]), "+f"(c[2]), "+f"(c[3])
        : "r"(a0), "r"(a1), "r"(a2), "r"(a3), "r"(b0), "r"(b1));
}

template <int KSTEPS, int LDA, int LDB>
__device__ __forceinline__ void gemm16x32(const __nv_bfloat16* __restrict__ A,
                                          const __nv_bfloat16* __restrict__ B,
                                          int m0, int n0, int lane, float c[4][4])
{
    const int l7 = lane & 7, s8 = (lane >> 3) & 1, s16 = (lane >> 4) & 1;
    unsigned aA  = sm_u32(A + (m0 + s8 * 8 + l7) * LDA + s16 * 8);
    unsigned aB0 = sm_u32(B + (n0 + s16 * 8 + l7) * LDB + s8 * 8);
    unsigned aB1 = aB0 + 16 * LDB * 2;
#pragma unroll
    for (int ks = 0; ks < KSTEPS; ++ks) {
        unsigned a0, a1, a2, a3, b0, b1, b2, b3;
        ldsm4(aA + ks * 32, a0, a1, a2, a3);
        ldsm4(aB0 + ks * 32, b0, b1, b2, b3);
        mmabf(c[0], a0, a1, a2, a3, b0, b1);
        mmabf(c[1], a0, a1, a2, a3, b2, b3);
        ldsm4(aB1 + ks * 32, b0, b1, b2, b3);
        mmabf(c[2], a0, a1, a2, a3, b0, b1);
        mmabf(c[3], a0, a1, a2, a3, b2, b3);
    }
}

template <int KSTEPS, int LDA, int LDB>
__device__ __forceinline__ void gemm32x32(const __nv_bfloat16* __restrict__ A,
                                          const __nv_bfloat16* __restrict__ B,
                                          int m0, int n0, int lane, float c[2][4][4])
{
    const int l7 = lane & 7, s8 = (lane >> 3) & 1, s16 = (lane >> 4) & 1;
    unsigned aA0 = sm_u32(A + (m0 + s8 * 8 + l7) * LDA + s16 * 8);
    unsigned aA1 = aA0 + 16 * LDA * 2;
    unsigned aB0 = sm_u32(B + (n0 + s16 * 8 + l7) * LDB + s8 * 8);
    unsigned aB1 = aB0 + 16 * LDB * 2;
#pragma unroll
    for (int ks = 0; ks < KSTEPS; ++ks) {
        unsigned a00, a01, a02, a03, a10, a11, a12, a13, b0, b1, b2, b3;
        ldsm4(aA0 + ks * 32, a00, a01, a02, a03);
        ldsm4(aA1 + ks * 32, a10, a11, a12, a13);
        ldsm4(aB0 + ks * 32, b0, b1, b2, b3);
        mmabf(c[0][0], a00, a01, a02, a03, b0, b1);
        mmabf(c[0][1], a00, a01, a02, a03, b2, b3);
        mmabf(c[1][0], a10, a11, a12, a13, b0, b1);
        mmabf(c[1][1], a10, a11, a12, a13, b2, b3);
        ldsm4(aB1 + ks * 32, b0, b1, b2, b3);
        mmabf(c[0][2], a00, a01, a02, a03, b0, b1);
        mmabf(c[0][3], a00, a01, a02, a03, b2, b3);
        mmabf(c[1][2], a10, a11, a12, a13, b0, b1);
        mmabf(c[1][3], a10, a11, a12, a13, b2, b3);
    }
}

__device__ __forceinline__ void st_bf2(__nv_bfloat16* p, float x, float y)
{
    __nv_bfloat162 v = __floats2bfloat162_rn(x, y);
    *reinterpret_cast<__nv_bfloat162*>(p) = v;
}

__device__ __forceinline__ unsigned pack_bf2(float x, float y)
{
    __nv_bfloat162 v = __floats2bfloat162_rn(x, y);
    return *reinterpret_cast<unsigned*>(&v);
}

// stage a 96x96 bf16 weight block into smem stride 104
__device__ __forceinline__ void stage_w(__nv_bfloat16* dst, const __nv_bfloat16* src,
                                        int tid, int nthr)
{
    for (int idx = tid; idx < 96 * 12; idx += nthr) {
        int r = idx / 12, q = idx % 12;
        cpa16(dst + r * 104 + q * 8, src + r * 96 + q * 8);
    }
}

// ---------------- kernel 1 smem layout (bytes) ----------------
#define A_XN 0          // XN; Wproj for the proj phase
#define A_K  23296      // Wv staging, then K
#define A_V  46592      // V
#define A_AO 69888      // Wk staging, then AO
#define A_W  93184      // Wq (resident through flash)
#define SM1_BYTES 113152

// K/V gemm part: C[112x96] with zeroed pad rows
__device__ __forceinline__ void qkv_part(const __nv_bfloat16* XN, const __nv_bfloat16* W,
                                         __nv_bfloat16* DST, const float* qkv_b,
                                         int bias_off, int wid, int lane, int g, int t4)
{
    for (int mac = wid; mac < 21; mac += 8) {
        int mt = mac / 3, nt = mac % 3;
        int m0 = mt * 16, n0 = nt * 32;
        float c[4][4] = {};
        gemm16x32<6, 104, 104>(XN, W, m0, n0, lane, c);
#pragma unroll
        for (int nn = 0; nn < 4; ++nn) {
            int d = n0 + nn * 8 + 2 * t4;
            float b0 = __ldg(&qkv_b[bias_off + d]);
            float b1 = __ldg(&qkv_b[bias_off + d + 1]);
#pragma unroll
            for (int rh = 0; rh < 2; ++rh) {
                int trow = m0 + g + rh * 8;
                float v0 = c[nn][rh * 2]     + b0;
                float v1 = c[nn][rh * 2 + 1] + b1;
                if (trow >= 98) { v0 = 0.f; v1 = 0.f; }   // K/V pads are reduction dims
                st_bf2(DST + trow * 104 + d, v0, v1);
            }
        }
    }
}

__global__ __launch_bounds__(256, 2)
void attn_kernel(const float* __restrict__ x,
                 const float* __restrict__ n1w, const float* __restrict__ n1b,
                 const float* __restrict__ qkv_b, const float* __restrict__ proj_b)
{
    extern __shared__ char smc[];
    __nv_bfloat16* XN = (__nv_bfloat16*)(smc + A_XN);
    __nv_bfloat16* Kb = (__nv_bfloat16*)(smc + A_K);
    __nv_bfloat16* V  = (__nv_bfloat16*)(smc + A_V);
    __nv_bfloat16* AO = (__nv_bfloat16*)(smc + A_AO);
    __nv_bfloat16* W  = (__nv_bfloat16*)(smc + A_W);
    __shared__ int s_toff[98];

    const int tid = threadIdx.x;
    const int wid = tid >> 5, lane = tid & 31;
    const int g = lane >> 2, t4 = lane & 3;

    // prefetch Wv (into K-buf) and Wq (into W) behind LN
    stage_w(Kb, g_wqkv + 18432, tid, 256);
    stage_w(W, g_wqkv, tid, 256);
    CPA_COMMIT();

    const int widx = blockIdx.x;
    const int b = widx >> 8;
    const int rr = widx & 255;
    const int dblk = rr >> 6, hblk = (rr >> 3) & 7, wblk = rr & 7;
    if (tid < 98) {
        int wd = (tid >= 49);
        int rem = tid - wd * 49;
        int wh = rem / 7, ww = rem - wh * 7;
        s_toff[tid] = (((b * 8 + dblk * 2 + wd) * 56 + hblk * 7 + wh) * 56 + wblk * 7 + ww) * 96;
    }
    // zero XN pad rows (keeps the Q-garbage path finite)
    for (int i = tid; i < 14 * 52; i += 256)
        reinterpret_cast<unsigned*>(XN + 98 * 104)[i] = 0u;
    __syncthreads();   // S1

    // ---- LN1 -> XN bf16 [t][c] ----
    for (int t = wid; t < 98; t += 8) {
        int off = s_toff[t];
        float v0 = x[off + lane];
        float v1 = x[off + lane + 32];
        float v2 = x[off + lane + 64];
        float s = v0 + v1 + v2;
#pragma unroll
        for (int o = 16; o; o >>= 1) s += __shfl_xor_sync(0xffffffffu, s, o);
        float mean = s * (1.f / 96.f);
        float d0 = v0 - mean, d1 = v1 - mean, d2 = v2 - mean;
        float q2 = d0 * d0 + d1 * d1 + d2 * d2;
#pragma unroll
        for (int o = 16; o; o >>= 1) q2 += __shfl_xor_sync(0xffffffffu, q2, o);
        float rstd = rsqrtf(q2 * (1.f / 96.f) + 1e-5f);
        XN[t * 104 + lane] =
            __float2bfloat16_rn(d0 * rstd * __ldg(&n1w[lane]) + __ldg(&n1b[lane]));
        XN[t * 104 + lane + 32] =
            __float2bfloat16_rn(d1 * rstd * __ldg(&n1w[lane + 32]) + __ldg(&n1b[lane + 32]));
        XN[t * 104 + lane + 64] =
            __float2bfloat16_rn(d2 * rstd * __ldg(&n1w[lane + 64]) + __ldg(&n1b[lane + 64]));
    }
    CPA_WAIT0();
    __syncthreads();   // S2: XN + Wv + Wq ready

    stage_w(AO, g_wqkv + 9216, tid, 256);    // Wk (hidden behind V gemm)
    CPA_COMMIT();
    qkv_part(XN, Kb, V, qkv_b, 192, wid, lane, g, t4);   // V = XN * Wv
    CPA_WAIT0();
    __syncthreads();   // S3: V + Wk ready; K-buf (Wv) dead

    qkv_part(XN, AO, Kb, qkv_b, 96, wid, lane, g, t4);   // K = XN * Wk
    __syncthreads();   // S4: K ready; AO (Wk) dead

    // ---- flash attention: Q in registers ----
    const int l7 = lane & 7;
    for (int unit = wid; unit < 21; unit += 8) {
        int h = unit / 7, m0 = (unit % 7) * 16;
        const __nv_bfloat16* Kh = Kb + h * 32;

        // Q tile in C-fragments: cq = XN[m0..m0+15][:] * Wq[:, h*32..h*32+31]
        float cq[4][4] = {};
        gemm16x32<6, 104, 104>(XN, W, m0, h * 32, lane, cq);

        // bias + scale in fragment space, pack straight into A-frags
        unsigned qa[2][4];
        {
            float qb0[4], qb1[4];
#pragma unroll
            for (int nn = 0; nn < 4; ++nn) {
                int d = h * 32 + nn * 8 + 2 * t4;
                qb0[nn] = __ldg(&qkv_b[d]);
                qb1[nn] = __ldg(&qkv_b[d + 1]);
            }
#pragma unroll
            for (int ks = 0; ks < 2; ++ks) {
                qa[ks][0] = pack_bf2((cq[2*ks][0] + qb0[2*ks]) * SCALEL,
                                     (cq[2*ks][1] + qb1[2*ks]) * SCALEL);
                qa[ks][1] = pack_bf2((cq[2*ks][2] + qb0[2*ks]) * SCALEL,
                                     (cq[2*ks][3] + qb1[2*ks]) * SCALEL);
                qa[ks][2] = pack_bf2((cq[2*ks+1][0] + qb0[2*ks+1]) * SCALEL,
                                     (cq[2*ks+1][1] + qb1[2*ks+1]) * SCALEL);
                qa[ks][3] = pack_bf2((cq[2*ks+1][2] + qb0[2*ks+1]) * SCALEL,
                                     (cq[2*ks+1][3] + qb1[2*ks+1]) * SCALEL);
            }
        }

        // S strip [16 x 112]
        float s[7][2][4];
#pragma unroll
        for (int j = 0; j < 7; ++j) {
#pragma unroll
            for (int hf = 0; hf < 2; ++hf)
#pragma unroll
                for (int e = 0; e < 4; ++e) s[j][hf][e] = 0.f;
            unsigned aB = sm_u32(Kh + (j * 16 + ((lane >> 4) & 1) * 8 + l7) * 104 +
                                 ((lane >> 3) & 1) * 8);
#pragma unroll
            for (int ks = 0; ks < 2; ++ks) {
                unsigned b0, b1, b2, b3;
                ldsm4(aB + ks * 32, b0, b1, b2, b3);
                mmabf(s[j][0], qa[ks][0], qa[ks][1], qa[ks][2], qa[ks][3], b0, b1);
                mmabf(s[j][1], qa[ks][0], qa[ks][1], qa[ks][2], qa[ks][3], b2, b3);
            }
        }

        // branchless bias + softmax (log2 domain)
        int i0 = m0 + g;     if (i0 > 97) i0 = 97;
        int i1 = m0 + g + 8; if (i1 > 97) i1 = 97;
        const __nv_bfloat16* bi0 = g_bias_bf + h * 10976 + i0 * 112;
        const __nv_bfloat16* bi1 = g_bias_bf + h * 10976 + i1 * 112;
        float mx0 = -1e30f, mx1 = -1e30f;
#pragma unroll
        for (int j = 0; j < 7; ++j) {
#pragma unroll
            for (int hf = 0; hf < 2; ++hf) {
                int col = 16 * j + 8 * hf + 2 * t4;
                __nv_bfloat162 b0 = *reinterpret_cast<const __nv_bfloat162*>(bi0 + col);
                __nv_bfloat162 b1 = *reinterpret_cast<const __nv_bfloat162*>(bi1 + col);
                s[j][hf][0] += __bfloat162float(b0.x);
                s[j][hf][1] += __bfloat162float(b0.y);
                s[j][hf][2] += __bfloat162float(b1.x);
                s[j][hf][3] += __bfloat162float(b1.y);
                mx0 = fmaxf(mx0, fmaxf(s[j][hf][0], s[j][hf][1]));
                mx1 = fmaxf(mx1, fmaxf(s[j][hf][2], s[j][hf][3]));
            }
        }
        mx0 = fmaxf(mx0, __shfl_xor_sync(0xffffffffu, mx0, 1));
        mx0 = fmaxf(mx0, __shfl_xor_sync(0xffffffffu, mx0, 2));
        mx1 = fmaxf(mx1, __shfl_xor_sync(0xffffffffu, mx1, 1));
        mx1 = fmaxf(mx1, __shfl_xor_sync(0xffffffffu, mx1, 2));
        float sum0 = 0.f, sum1 = 0.f;
#pragma unroll
        for (int j = 0; j < 7; ++j)
#pragma unroll
            for (int hf = 0; hf < 2; ++hf) {
                s[j][hf][0] = ex2f(s[j][hf][0] - mx0);
                s[j][hf][1] = ex2f(s[j][hf][1] - mx0);
                s[j][hf][2] = ex2f(s[j][hf][2] - mx1);
                s[j][hf][3] = ex2f(s[j][hf][3] - mx1);
                sum0 += s[j][hf][0] + s[j][hf][1];
                sum1 += s[j][hf][2] + s[j][hf][3];
            }
        sum0 += __shfl_xor_sync(0xffffffffu, sum0, 1);
        sum0 += __shfl_xor_sync(0xffffffffu, sum0, 2);
        sum1 += __shfl_xor_sync(0xffffffffu, sum1, 1);
        sum1 += __shfl_xor_sync(0xffffffffu, sum1, 2);
        float r0 = __fdividef(1.f, sum0), r1 = __fdividef(1.f, sum1);

        unsigned pa[7][4];
#pragma unroll
        for (int j = 0; j < 7; ++j) {
            pa[j][0] = pack_bf2(s[j][0][0] * r0, s[j][0][1] * r0);
            pa[j][1] = pack_bf2(s[j][0][2] * r1, s[j][0][3] * r1);
            pa[j][2] = pack_bf2(s[j][1][0] * r0, s[j][1][1] * r0);
            pa[j][3] = pack_bf2(s[j][1][2] * r1, s[j][1][3] * r1);
        }

        float o[2][2][4] = {};
#pragma unroll
        for (int j = 0; j < 7; ++j) {
            unsigned vb = sm_u32(V + (j * 16 + ((lane >> 3) & 1) * 8 + l7) * 104 +
                                 h * 32 + ((lane >> 4) & 1) * 8);
            unsigned b0, b1, b2, b3;
            ldsm4t(vb, b0, b1, b2, b3);
            mmabf(o[0][0], pa[j][0], pa[j][1], pa[j][2], pa[j][3], b0, b1);
            mmabf(o[0][1], pa[j][0], pa[j][1], pa[j][2], pa[j][3], b2, b3);
            ldsm4t(vb + 32, b0, b1, b2, b3);
            mmabf(o[1][0], pa[j][0], pa[j][1], pa[j][2], pa[j][3], b0, b1);
            mmabf(o[1][1], pa[j][0], pa[j][1], pa[j][2], pa[j][3], b2, b3);
        }

#pragma unroll
        for (int nc = 0; nc < 2; ++nc)
#pragma unroll
            for (int hf = 0; hf < 2; ++hf) {
                int col = h * 32 + nc * 16 + hf * 8 + 2 * t4;
#pragma unroll
                for (int rh = 0; rh < 2; ++rh)
                    st_bf2(AO + (m0 + g + rh * 8) * 104 + col,
                           o[nc][hf][rh * 2], o[nc][hf][rh * 2 + 1]);
            }
    }
    __syncthreads();   // S5: flash done; XN dead

    // stage Wproj into XN region
    stage_w(XN, g_wproj, tid, 256);
    CPA_COMMIT();
    CPA_WAIT0();
    __syncthreads();   // S6: Wproj ready

    // ---- proj + bias + residual ----
    for (int mac = wid; mac < 21; mac += 8) {
        int mt = mac / 3, nt = mac % 3;
        int m0 = mt * 16, n0 = nt * 32;
        float c[4][4] = {};
        gemm16x32<6, 104, 104>(AO, XN, m0, n0, lane, c);
#pragma unroll
        for (int nn = 0; nn < 4; ++nn) {
            int col = n0 + nn * 8 + 2 * t4;
            float pb0 = __ldg(&proj_b[col]), pb1 = __ldg(&proj_b[col + 1]);
#pragma unroll
            for (int rh = 0; rh < 2; ++rh) {
                int trow = m0 + g + rh * 8;
                if (trow < 98) {
                    int off = s_toff[trow] + col;
                    float2 xr = *reinterpret_cast<const float2*>(&x[off]);
                    float2 o2;
                    o2.x = c[nn][rh * 2]     + pb0 + xr.x;
                    o2.y = c[nn][rh * 2 + 1] + pb1 + xr.y;
                    *reinterpret_cast<float2*>(&g_xmid[off]) = o2;
                }
            }
        }
    }
}

// ---------------- kernel 2 ----------------
#define M_X   0            // bf16 [128][104] = 26624
#define M_H   26624        // bf16 [128][104]
#define M_W1  53248        // bf16 [96][104]  = 19968
#define M_W2A 73216
#define M_W2B 93184
#define SM2_BYTES 113152

__device__ __forceinline__ float gelu_fast(float x)
{
    // tanh-form GELU via HW tanh; error far below bf16 quantization of h
    float u = x * x;
    float w = fmaf(0.03567740814f, u, 0.7978845608f);
    float t = tanhf_hw(x * w);
    return fmaf(x * 0.5f, t, x * 0.5f);
}

__global__ __launch_bounds__(384, 2)
void mlp_kernel(const float* __restrict__ n2w, const float* __restrict__ n2b,
                const float* __restrict__ fc1_b, const float* __restrict__ fc2_b,
                float* __restrict__ out)
{
    extern __shared__ char smc[];
    __nv_bfloat16* X  = (__nv_bfloat16*)(smc + M_X);
    __nv_bfloat16* H  = (__nv_bfloat16*)(smc + M_H);
    __nv_bfloat16* W1 = (__nv_bfloat16*)(smc + M_W1);
    __nv_bfloat16* W2buf[2] = { (__nv_bfloat16*)(smc + M_W2A), (__nv_bfloat16*)(smc + M_W2B) };

    const int tid = threadIdx.x;
    const int wid = tid >> 5, lane = tid & 31;
    const int g = lane >> 2, t4 = lane & 3;
    const int tbase = blockIdx.x * 128;

    const int mt = wid / 3, nt = wid % 3;
    const int m0 = mt * 32, n0 = nt * 32;

    // preload chunk-0 weights (hidden behind LN)
    stage_w(W1, g_fc1, tid, 384);
    for (int idx = tid; idx < 96 * 12; idx += 384) {
        int r = idx / 12, q = idx % 12;
        cpa16(W2buf[0] + r * 104 + q * 8, g_fc2 + r * 384 + q * 8);
    }
    CPA_COMMIT();

    // ---- LN2 -> X bf16 ----
    for (int t = wid; t < 128; t += 12) {
        const float* p = g_xmid + (tbase + t) * 96;
        float v0 = p[lane], v1 = p[lane + 32], v2 = p[lane + 64];
        float s = v0 + v1 + v2;
#pragma unroll
        for (int o = 16; o; o >>= 1) s += __shfl_xor_sync(0xffffffffu, s, o);
        float mean = s * (1.f / 96.f);
        float d0 = v0 - mean, d1 = v1 - mean, d2 = v2 - mean;
        float q2 = d0 * d0 + d1 * d1 + d2 * d2;
#pragma unroll
        for (int o = 16; o; o >>= 1) q2 += __shfl_xor_sync(0xffffffffu, q2, o);
        float rstd = rsqrtf(q2 * (1.f / 96.f) + 1e-5f);
        X[t * 104 + lane] =
            __float2bfloat16_rn(d0 * rstd * __ldg(&n2w[lane]) + __ldg(&n2b[lane]));
        X[t * 104 + lane + 32] =
            __float2bfloat16_rn(d1 * rstd * __ldg(&n2w[lane + 32]) + __ldg(&n2b[lane + 32]));
        X[t * 104 + lane + 64] =
            __float2bfloat16_rn(d2 * rstd * __ldg(&n2w[lane + 64]) + __ldg(&n2b[lane + 64]));
    }

    float c2[2][4][4] = {};   // persistent fc2 accumulators

    for (int ch = 0; ch < 4; ++ch) {
        CPA_WAIT0();
        __syncthreads();

        if (ch < 3) {
            for (int idx = tid; idx < 96 * 12; idx += 384) {
                int r = idx / 12, q = idx % 12;
                cpa16(W2buf[(ch + 1) & 1] + r * 104 + q * 8,
                      g_fc2 + r * 384 + (ch + 1) * 96 + q * 8);
            }
            CPA_COMMIT();
        }

        // fc1 tile + GELU -> H
        {
            float c[2][4][4] = {};
            gemm32x32<6, 104, 104>(X, W1, m0, n0, lane, c);
#pragma unroll
            for (int mf = 0; mf < 2; ++mf)
#pragma unroll
                for (int nn = 0; nn < 4; ++nn) {
                    int col = n0 + nn * 8 + 2 * t4;
                    float b0 = __ldg(&fc1_b[ch * 96 + col]);
                    float b1 = __ldg(&fc1_b[ch * 96 + col + 1]);
#pragma unroll
                    for (int rh = 0; rh < 2; ++rh)
                        st_bf2(H + (m0 + mf * 16 + g + rh * 8) * 104 + col,
                               gelu_fast(c[mf][nn][rh * 2] + b0),
                               gelu_fast(c[mf][nn][rh * 2 + 1] + b1));
                }
        }
        __syncthreads();

        if (ch < 3) {
            stage_w(W1, g_fc1 + (ch + 1) * 96 * 96, tid, 384);
            CPA_COMMIT();
        }

        gemm32x32<6, 104, 104>(H, W2buf[ch & 1], m0, n0, lane, c2);
    }

    // ---- epilogue: bias + residual -> out ----
#pragma unroll
    for (int mf = 0; mf < 2; ++mf)
#pragma unroll
        for (int nn = 0; nn < 4; ++nn) {
            int col = n0 + nn * 8 + 2 * t4;
            float b0 = __ldg(&fc2_b[col]), b1 = __ldg(&fc2_b[col + 1]);
#pragma unroll
            for (int rh = 0; rh < 2; ++rh) {
                int off = (tbase + m0 + mf * 16 + g + rh * 8) * 96 + col;
                float2 xr = *reinterpret_cast<const float2*>(&g_xmid[off]);
                float2 o2;
                o2.x = c2[mf][nn][rh * 2]     + b0 + xr.x;
                o2.y = c2[mf][nn][rh * 2 + 1] + b1 + xr.y;
                *reinterpret_cast<float2*>(&out[off]) = o2;
            }
        }
}

// ---------------- launch ----------------
extern "C" void kernel_launch(void* const* d_in, const int* in_sizes, int n_in,
                              void* d_out, int out_size)
{
    const float* x      = (const float*)d_in[0];
    const float* n1w    = (const float*)d_in[1];
    const float* n1b    = (const float*)d_in[2];
    const float* qkv_w  = (const float*)d_in[3];
    const float* qkv_b  = (const float*)d_in[4];
    const float* proj_w = (const float*)d_in[5];
    const float* proj_b = (const float*)d_in[6];
    const float* rpb    = (const float*)d_in[7];
    const float* n2w    = (const float*)d_in[8];
    const float* n2b    = (const float*)d_in[9];
    const float* fc1_w  = (const float*)d_in[10];
    const float* fc1_b  = (const float*)d_in[11];
    const float* fc2_w  = (const float*)d_in[12];
    const float* fc2_b  = (const float*)d_in[13];
    float* out = (float*)d_out;

    cudaFuncSetAttribute(attn_kernel, cudaFuncAttributeMaxDynamicSharedMemorySize, SM1_BYTES);
    cudaFuncSetAttribute(mlp_kernel,  cudaFuncAttributeMaxDynamicSharedMemorySize, SM2_BYTES);

    prep_kernel<<<128, 256>>>(qkv_w, proj_w, fc1_w, fc2_w, rpb);
    attn_kernel<<<NWIN, 256, SM1_BYTES>>>(x, n1w, n1b, qkv_b, proj_b);
    mlp_kernel<<<NTOKENS / 128, 384, SM2_BYTES>>>(n2w, n2b, fc1_b, fc2_b, out);
}